// round 6
// baseline (speedup 1.0000x reference)
#include <cuda_runtime.h>
#include <cuda_bf16.h>

// Problem constants: B=4, T=32 -> BT=128 slices; N=512 nodes; F_in=D=128.
#define BT    128
#define NN    512
#define DD    128
#define NROWS (BT * NN)       // 65536 total node-rows

typedef unsigned long long u64;

// Scratch (allocation-free: __device__ globals)
__device__ __align__(16) float g_Wh[NROWS * DD];   // 33.5 MB
__device__ float g_es[NROWS], g_ed[NROWS];
__device__ float g_F[NROWS], g_f[NROWS];           // exp(es), exp(0.2*es)
__device__ float g_G[NROWS], g_g[NROWS];           // exp(ed), exp(0.2*ed)
__device__ unsigned g_adjbits[NN * 16];            // bit j%32 of word [i][j/32]

// ---- f32x2 packed-math helpers (sm_103a; ptxas won't emit FFMA2 from C++) ----
__device__ __forceinline__ u64 pack2(float lo, float hi) {
    u64 r; asm("mov.b64 %0, {%1, %2};" : "=l"(r) : "f"(lo), "f"(hi)); return r;
}
__device__ __forceinline__ void ffma2(u64& d, u64 a, u64 b) {
    asm("fma.rn.f32x2 %0, %1, %2, %0;" : "+l"(d) : "l"(a), "l"(b));
}
__device__ __forceinline__ void fadd2(u64& d, u64 a) {
    asm("add.rn.f32x2 %0, %0, %1;" : "+l"(d) : "l"(a));
}
__device__ __forceinline__ float2 unpack2(u64 v) {
    float2 f; asm("mov.b64 {%0, %1}, %2;" : "=f"(f.x), "=f"(f.y) : "l"(v)); return f;
}

// ---------------------------------------------------------------------------
// Kernel 1: Wh = h @ W  (M=65536, K=128, N=128), tile 64x128, f32x2 FMAs.
// Fused epilogue: per-row es/ed dot products + exp tables (replaces k_prep).
// ---------------------------------------------------------------------------
__global__ __launch_bounds__(256) void k_gemm(const float* __restrict__ h,
                                              const float* __restrict__ W,
                                              const float* __restrict__ a) {
    __shared__ float hs[64][33];         // +1 pad
    __shared__ float Ws[32][128];
    __shared__ float sred[64][17];       // es partials
    __shared__ float dred[64][17];       // ed partials

    const int row0 = blockIdx.x * 64;
    const int tid  = threadIdx.x;
    const int tx   = tid & 15;           // col group (8 cols)
    const int ty   = tid >> 4;           // row group (4 rows, stride 16)

    u64 acc2[4][4];
#pragma unroll
    for (int r = 0; r < 4; r++)
#pragma unroll
        for (int d = 0; d < 4; d++) acc2[r][d] = 0ull;

    for (int k0 = 0; k0 < 128; k0 += 32) {
        __syncthreads();
        // load 64x32 h chunk (512 float4, 2 per thread)
#pragma unroll
        for (int l = 0; l < 2; l++) {
            int idx = tid + l * 256;
            int r = idx >> 3, c4 = (idx & 7) * 4;
            float4 v = *(const float4*)&h[(size_t)(row0 + r) * 128 + k0 + c4];
            hs[r][c4 + 0] = v.x; hs[r][c4 + 1] = v.y;
            hs[r][c4 + 2] = v.z; hs[r][c4 + 3] = v.w;
        }
        // load 32x128 W chunk (1024 float4, 4 per thread)
#pragma unroll
        for (int l = 0; l < 4; l++) {
            int idx = tid + l * 256;
            int kk = idx >> 5, dc = (idx & 31) * 4;
            *(float4*)&Ws[kk][dc] = *(const float4*)&W[(k0 + kk) * 128 + dc];
        }
        __syncthreads();
#pragma unroll 8
        for (int k = 0; k < 32; k++) {
            ulonglong2 wa = *(const ulonglong2*)&Ws[k][tx * 8];
            ulonglong2 wb = *(const ulonglong2*)&Ws[k][tx * 8 + 4];
#pragma unroll
            for (int r = 0; r < 4; r++) {
                float hv = hs[ty + r * 16][k];
                u64 h2 = pack2(hv, hv);
                ffma2(acc2[r][0], h2, wa.x);
                ffma2(acc2[r][1], h2, wa.y);
                ffma2(acc2[r][2], h2, wb.x);
                ffma2(acc2[r][3], h2, wb.y);
            }
        }
    }

    // attention vector slices for this thread's 8 columns
    float a_s[8], a_d[8];
#pragma unroll
    for (int d = 0; d < 8; d++) {
        a_s[d] = a[tx * 8 + d];
        a_d[d] = a[128 + tx * 8 + d];
    }

#pragma unroll
    for (int r = 0; r < 4; r++) {
        int rl = ty + r * 16;
        float v[8];
        float2 p;
        p = unpack2(acc2[r][0]); v[0] = p.x; v[1] = p.y;
        p = unpack2(acc2[r][1]); v[2] = p.x; v[3] = p.y;
        p = unpack2(acc2[r][2]); v[4] = p.x; v[5] = p.y;
        p = unpack2(acc2[r][3]); v[6] = p.x; v[7] = p.y;
        float4 o0 = make_float4(v[0], v[1], v[2], v[3]);
        float4 o1 = make_float4(v[4], v[5], v[6], v[7]);
        float* dst = g_Wh + (size_t)(row0 + rl) * 128 + tx * 8;
        *(float4*)dst = o0;
        *(float4*)(dst + 4) = o1;
        float s = 0.f, dd = 0.f;
#pragma unroll
        for (int d = 0; d < 8; d++) { s += v[d] * a_s[d]; dd += v[d] * a_d[d]; }
        sred[rl][tx] = s;
        dred[rl][tx] = dd;
    }
    __syncthreads();
    if (tid < 64) {
        float s = 0.f, dd = 0.f;
#pragma unroll
        for (int t = 0; t < 16; t++) { s += sred[tid][t]; dd += dred[tid][t]; }
        int n = row0 + tid;
        g_es[n] = s;  g_ed[n] = dd;
        g_F[n] = expf(s);         g_f[n] = expf(0.2f * s);
        g_G[n] = expf(dd);        g_g[n] = expf(0.2f * dd);
    }
}

// ---------------------------------------------------------------------------
// Kernel 2: adjacency -> bitmask (adj shared across all bt slices)
// ---------------------------------------------------------------------------
__global__ __launch_bounds__(256) void k_adjbits(const int* __restrict__ adj) {
    int idx = blockIdx.x * 256 + threadIdx.x;   // 8192 words
    int i = idx >> 4, w = idx & 15;
    unsigned bits = 0;
#pragma unroll
    for (int b = 0; b < 32; b++)
        if (adj[i * NN + w * 32 + b] > 0) bits |= (1u << b);
    g_adjbits[idx] = bits;
}

// ---------------------------------------------------------------------------
// Kernel 3: fused masked-softmax-attention @ Wh.
// c_ij = adj_ij * ((es_i+ed_j > 0) ? F_i*G_j : f_i*g_j)   (separable exp)
// out_i = (sum_j c_ij * Wh_j) / (sum_j c_ij)
// Per chunk: Phase A builds the 64x64 coefficient tile in shared as {c,c}
// f32x2 pairs; Phase B is a pure FFMA2 GEMM (16 FFMA2 + 4 ADD2 per jj).
// Dynamic smem: Whs 32768 B + Cs 64*66*8 = 33792 B -> 66560 B.
// ---------------------------------------------------------------------------
__global__ __launch_bounds__(256) void k_attn(float* __restrict__ out) {
    extern __shared__ char sm_raw[];
    float* Whs = (float*)sm_raw;                  // [64][128]
    u64*   Cs  = (u64*)(sm_raw + 64 * 128 * 4);   // [64][66] (pad 2)

    const int bt   = blockIdx.x >> 3;
    const int tile = blockIdx.x & 7;
    const int base = bt * NN;
    const int i0   = tile * 64;
    const int tid  = threadIdx.x;
    const int tx   = tid & 15;
    const int ty   = tid >> 4;

    // Phase-A identity: thread owns row i_l, 16 j's starting at q*16
    const int i_l = tid >> 2;
    const int q   = tid & 3;
    const int gi  = base + i0 + i_l;
    const float esv = g_es[gi];
    const float Fv  = g_F[gi];
    const float fv  = g_f[gi];

    u64 acc2[4][4], den2[4];
#pragma unroll
    for (int r = 0; r < 4; r++) {
        den2[r] = 0ull;
#pragma unroll
        for (int d = 0; d < 4; d++) acc2[r][d] = 0ull;
    }

    for (int j0 = 0; j0 < NN; j0 += 64) {
        __syncthreads();
        // fill Whs (2048 float4, 8 per thread)
        {
            const float4* src = (const float4*)(g_Wh + (size_t)(base + j0) * 128);
            float4* dst = (float4*)Whs;
#pragma unroll
            for (int l = 0; l < 8; l++) dst[tid + l * 256] = src[tid + l * 256];
        }
        // Phase A: 64x64 coefficient tile, duplicated f32x2
        {
            unsigned bits = g_adjbits[(i0 + i_l) * 16 + (j0 >> 5) + (q >> 1)]
                            >> ((q & 1) * 16);
            int nb = base + j0 + q * 16;
            u64* crow = Cs + i_l * 66 + q * 16;
#pragma unroll
            for (int j = 0; j < 16; j++) {
                float ed = g_ed[nb + j];
                float Gv = g_G[nb + j];
                float gv = g_g[nb + j];
                float t = esv + ed;
                float c = (t > 0.f) ? (Fv * Gv) : (fv * gv);
                c = ((bits >> j) & 1u) ? c : 0.f;
                crow[j] = pack2(c, c);
            }
        }
        __syncthreads();

        // Phase B: GEMM on packed coefficients
#pragma unroll 4
        for (int jj = 0; jj < 64; jj++) {
            u64 cr[4];
#pragma unroll
            for (int r = 0; r < 4; r++) cr[r] = Cs[(ty + r * 16) * 66 + jj];
            const ulonglong2* wp = (const ulonglong2*)(Whs + jj * 128 + tx * 8);
            ulonglong2 wa = wp[0], wb = wp[1];
#pragma unroll
            for (int r = 0; r < 4; r++) {
                fadd2(den2[r], cr[r]);
                ffma2(acc2[r][0], cr[r], wa.x);
                ffma2(acc2[r][1], cr[r], wa.y);
                ffma2(acc2[r][2], cr[r], wb.x);
                ffma2(acc2[r][3], cr[r], wb.y);
            }
        }
    }

#pragma unroll
    for (int r = 0; r < 4; r++) {
        float inv = 1.0f / unpack2(den2[r]).x;
        float2 p0 = unpack2(acc2[r][0]);
        float2 p1 = unpack2(acc2[r][1]);
        float2 p2 = unpack2(acc2[r][2]);
        float2 p3 = unpack2(acc2[r][3]);
        float4 o0 = make_float4(p0.x * inv, p0.y * inv, p1.x * inv, p1.y * inv);
        float4 o1 = make_float4(p2.x * inv, p2.y * inv, p3.x * inv, p3.y * inv);
        float* dst = out + (size_t)(base + i0 + ty + r * 16) * 128 + tx * 8;
        *(float4*)dst = o0;
        *(float4*)(dst + 4) = o1;
    }
}

// ---------------------------------------------------------------------------
extern "C" void kernel_launch(void* const* d_in, const int* in_sizes, int n_in,
                              void* d_out, int out_size) {
    const float* h   = (const float*)d_in[0];   // (4,32,512,128) f32
    const int*   adj = (const int*)d_in[1];     // (512,512) i32
    const float* W   = (const float*)d_in[2];   // (128,128) f32
    const float* a   = (const float*)d_in[3];   // (256,) f32
    float* out = (float*)d_out;                 // (4,32,512,128) f32

    const int attn_smem = 64 * 128 * 4 + 64 * 66 * 8;   // 66560 B
    cudaFuncSetAttribute(k_attn, cudaFuncAttributeMaxDynamicSharedMemorySize,
                         attn_smem);

    k_gemm<<<NROWS / 64, 256>>>(h, W, a);           // Wh + es/ed/exp tables
    k_adjbits<<<(NN * 16) / 256, 256>>>(adj);       // adj bitmask
    k_attn<<<BT * 8, 256, attn_smem>>>(out);        // fused softmax-attention
}

// round 7
// speedup vs baseline: 1.1586x; 1.1586x over previous
#include <cuda_runtime.h>
#include <cuda_bf16.h>

// Problem constants: B=4, T=32 -> BT=128 slices; N=512 nodes; F_in=D=128.
#define BT    128
#define NN    512
#define DD    128
#define NROWS (BT * NN)       // 65536 total node-rows

typedef unsigned long long u64;

// Scratch (allocation-free: __device__ globals)
__device__ __align__(16) float g_Wh[NROWS * DD];   // 33.5 MB
__device__ float g_es[NROWS], g_ed[NROWS];
__device__ float g_F[NROWS], g_f[NROWS];           // exp(es), exp(0.2*es)
__device__ float g_G[NROWS], g_g[NROWS];           // exp(ed), exp(0.2*ed)
__device__ unsigned g_adjbits[NN * 16];            // bit j%32 of word [i][j/32]

// ---- f32x2 helpers (kept ONLY for k_gemm, measured at 87us) ----
__device__ __forceinline__ u64 pack2(float lo, float hi) {
    u64 r; asm("mov.b64 %0, {%1, %2};" : "=l"(r) : "f"(lo), "f"(hi)); return r;
}
__device__ __forceinline__ void ffma2(u64& d, u64 a, u64 b) {
    asm("fma.rn.f32x2 %0, %1, %2, %0;" : "+l"(d) : "l"(a), "l"(b));
}
__device__ __forceinline__ float2 unpack2(u64 v) {
    float2 f; asm("mov.b64 {%0, %1}, %2;" : "=f"(f.x), "=f"(f.y) : "l"(v)); return f;
}

// ---------------------------------------------------------------------------
// Kernel 1: Wh = h @ W  (M=65536, K=128, N=128), tile 64x128.
// Fused epilogue: per-row es/ed dot products + exp tables.
// ---------------------------------------------------------------------------
__global__ __launch_bounds__(256) void k_gemm(const float* __restrict__ h,
                                              const float* __restrict__ W,
                                              const float* __restrict__ a) {
    __shared__ float hs[64][33];         // +1 pad
    __shared__ float Ws[32][128];
    __shared__ float sred[64][17];       // es partials
    __shared__ float dred[64][17];       // ed partials

    const int row0 = blockIdx.x * 64;
    const int tid  = threadIdx.x;
    const int tx   = tid & 15;           // col group (8 cols)
    const int ty   = tid >> 4;           // row group (4 rows, stride 16)

    u64 acc2[4][4];
#pragma unroll
    for (int r = 0; r < 4; r++)
#pragma unroll
        for (int d = 0; d < 4; d++) acc2[r][d] = 0ull;

    for (int k0 = 0; k0 < 128; k0 += 32) {
        __syncthreads();
#pragma unroll
        for (int l = 0; l < 2; l++) {
            int idx = tid + l * 256;
            int r = idx >> 3, c4 = (idx & 7) * 4;
            float4 v = *(const float4*)&h[(size_t)(row0 + r) * 128 + k0 + c4];
            hs[r][c4 + 0] = v.x; hs[r][c4 + 1] = v.y;
            hs[r][c4 + 2] = v.z; hs[r][c4 + 3] = v.w;
        }
#pragma unroll
        for (int l = 0; l < 4; l++) {
            int idx = tid + l * 256;
            int kk = idx >> 5, dc = (idx & 31) * 4;
            *(float4*)&Ws[kk][dc] = *(const float4*)&W[(k0 + kk) * 128 + dc];
        }
        __syncthreads();
#pragma unroll 8
        for (int k = 0; k < 32; k++) {
            ulonglong2 wa = *(const ulonglong2*)&Ws[k][tx * 8];
            ulonglong2 wb = *(const ulonglong2*)&Ws[k][tx * 8 + 4];
#pragma unroll
            for (int r = 0; r < 4; r++) {
                float hv = hs[ty + r * 16][k];
                u64 h2 = pack2(hv, hv);
                ffma2(acc2[r][0], h2, wa.x);
                ffma2(acc2[r][1], h2, wa.y);
                ffma2(acc2[r][2], h2, wb.x);
                ffma2(acc2[r][3], h2, wb.y);
            }
        }
    }

    float a_s[8], a_d[8];
#pragma unroll
    for (int d = 0; d < 8; d++) {
        a_s[d] = a[tx * 8 + d];
        a_d[d] = a[128 + tx * 8 + d];
    }

#pragma unroll
    for (int r = 0; r < 4; r++) {
        int rl = ty + r * 16;
        float v[8];
        float2 p;
        p = unpack2(acc2[r][0]); v[0] = p.x; v[1] = p.y;
        p = unpack2(acc2[r][1]); v[2] = p.x; v[3] = p.y;
        p = unpack2(acc2[r][2]); v[4] = p.x; v[5] = p.y;
        p = unpack2(acc2[r][3]); v[6] = p.x; v[7] = p.y;
        float* dst = g_Wh + (size_t)(row0 + rl) * 128 + tx * 8;
        *(float4*)dst     = make_float4(v[0], v[1], v[2], v[3]);
        *(float4*)(dst+4) = make_float4(v[4], v[5], v[6], v[7]);
        float s = 0.f, dd = 0.f;
#pragma unroll
        for (int d = 0; d < 8; d++) { s += v[d] * a_s[d]; dd += v[d] * a_d[d]; }
        sred[rl][tx] = s;
        dred[rl][tx] = dd;
    }
    __syncthreads();
    if (tid < 64) {
        float s = 0.f, dd = 0.f;
#pragma unroll
        for (int t = 0; t < 16; t++) { s += sred[tid][t]; dd += dred[tid][t]; }
        int n = row0 + tid;
        g_es[n] = s;  g_ed[n] = dd;
        g_F[n] = expf(s);         g_f[n] = expf(0.2f * s);
        g_G[n] = expf(dd);        g_g[n] = expf(0.2f * dd);
    }
}

// ---------------------------------------------------------------------------
// Kernel 2: adjacency -> bitmask
// ---------------------------------------------------------------------------
__global__ __launch_bounds__(256) void k_adjbits(const int* __restrict__ adj) {
    int idx = blockIdx.x * 256 + threadIdx.x;   // 8192 words
    int i = idx >> 4, w = idx & 15;
    unsigned bits = 0;
#pragma unroll
    for (int b = 0; b < 32; b++)
        if (adj[i * NN + w * 32 + b] > 0) bits |= (1u << b);
    g_adjbits[idx] = bits;
}

// ---------------------------------------------------------------------------
// Kernel 3: fused masked-softmax-attention @ Wh.
// c_ij = adj_ij * ((es_i+ed_j > 0) ? F_i*G_j : f_i*g_j)   (separable exp)
// out_i = (sum_j c_ij * Wh_j) / (sum_j c_ij)
// Phase A: build 64x64 float coefficient tile (coalesced, scalar).
// Phase B: scalar-FFMA GEMM; Cs read vectorized (1 LDS.128 per row per 4 jj).
// Dynamic smem: Whs 64*128*4 = 32768 B + Cs 64*68*4 = 17408 B -> 50176 B.
// ---------------------------------------------------------------------------
__global__ __launch_bounds__(256) void k_attn(float* __restrict__ out) {
    extern __shared__ char sm_raw[];
    float* Whs = (float*)sm_raw;                   // [64][128]
    float* Cs  = (float*)(sm_raw + 64 * 128 * 4);  // [64][68] (pad->16B-aligned rows)

    __shared__ float    esS[64], FS[64], fS[64];
    __shared__ unsigned bitsS[64][16];

    const int bt   = blockIdx.x >> 3;
    const int tile = blockIdx.x & 7;
    const int base = bt * NN;
    const int i0   = tile * 64;
    const int tid  = threadIdx.x;
    const int tx   = tid & 15;
    const int ty   = tid >> 4;

    // preload per-row tables + adjacency words for this block's 64 rows
    if (tid < 64) {
        int n = base + i0 + tid;
        esS[tid] = g_es[n]; FS[tid] = g_F[n]; fS[tid] = g_f[n];
    }
    {   // 64*16 = 1024 words, 4 per thread
        int idx = tid * 4;
        int r = idx >> 4, w = idx & 15;
        *(uint4*)&bitsS[r][w] = *(const uint4*)&g_adjbits[(i0 + r) * 16 + w];
    }

    // Phase-A identity: thread owns column j_l, rows rq*16 .. rq*16+15
    const int j_l = tid & 63;
    const int rq  = tid >> 6;

    float den[4];
    float acc[4][8];
#pragma unroll
    for (int r = 0; r < 4; r++) {
        den[r] = 0.f;
#pragma unroll
        for (int d = 0; d < 8; d++) acc[r][d] = 0.f;
    }

    for (int j0 = 0; j0 < NN; j0 += 64) {
        __syncthreads();
        // fill Whs (2048 float4, 8 per thread; coalesced)
        {
            const float4* src = (const float4*)(g_Wh + (size_t)(base + j0) * 128);
            float4* dst = (float4*)Whs;
#pragma unroll
            for (int l = 0; l < 8; l++) dst[tid + l * 256] = src[tid + l * 256];
        }
        // Phase A: coefficients for column j_l, 16 rows (coalesced j-side loads)
        {
            int nj = base + j0 + j_l;
            float ed = g_ed[nj], Gv = g_G[nj], gv = g_g[nj];
            const int w   = (j0 >> 5) + (j_l >> 5);
            const int bit = j_l & 31;
#pragma unroll
            for (int r2 = 0; r2 < 16; r2++) {
                int il = rq * 16 + r2;
                float t = esS[il] + ed;
                float c = (t > 0.f) ? (FS[il] * Gv) : (fS[il] * gv);
                c = ((bitsS[il][w] >> bit) & 1u) ? c : 0.f;
                Cs[il * 68 + j_l] = c;
            }
        }
        __syncthreads();

        // Phase B: scalar-FFMA GEMM, Cs vectorized per 4 jj
#pragma unroll 2
        for (int jj = 0; jj < 64; jj += 4) {
            float4 c4[4];
#pragma unroll
            for (int r = 0; r < 4; r++)
                c4[r] = *(const float4*)&Cs[(ty + r * 16) * 68 + jj];
#pragma unroll
            for (int u = 0; u < 4; u++) {
                const float4* wp = (const float4*)(Whs + (jj + u) * 128 + tx * 8);
                float4 w0 = wp[0], w1 = wp[1];
#pragma unroll
                for (int r = 0; r < 4; r++) {
                    float c = (u == 0) ? c4[r].x : (u == 1) ? c4[r].y
                            : (u == 2) ? c4[r].z : c4[r].w;
                    den[r] += c;
                    acc[r][0] += c * w0.x; acc[r][1] += c * w0.y;
                    acc[r][2] += c * w0.z; acc[r][3] += c * w0.w;
                    acc[r][4] += c * w1.x; acc[r][5] += c * w1.y;
                    acc[r][6] += c * w1.z; acc[r][7] += c * w1.w;
                }
            }
        }
    }

#pragma unroll
    for (int r = 0; r < 4; r++) {
        float inv = 1.0f / den[r];
        float* dst = out + (size_t)(base + i0 + ty + r * 16) * 128 + tx * 8;
        *(float4*)dst     = make_float4(acc[r][0] * inv, acc[r][1] * inv,
                                        acc[r][2] * inv, acc[r][3] * inv);
        *(float4*)(dst+4) = make_float4(acc[r][4] * inv, acc[r][5] * inv,
                                        acc[r][6] * inv, acc[r][7] * inv);
    }
}

// ---------------------------------------------------------------------------
extern "C" void kernel_launch(void* const* d_in, const int* in_sizes, int n_in,
                              void* d_out, int out_size) {
    const float* h   = (const float*)d_in[0];   // (4,32,512,128) f32
    const int*   adj = (const int*)d_in[1];     // (512,512) i32
    const float* W   = (const float*)d_in[2];   // (128,128) f32
    const float* a   = (const float*)d_in[3];   // (256,) f32
    float* out = (float*)d_out;                 // (4,32,512,128) f32

    const int attn_smem = 64 * 128 * 4 + 64 * 68 * 4;   // 50176 B
    cudaFuncSetAttribute(k_attn, cudaFuncAttributeMaxDynamicSharedMemorySize,
                         attn_smem);

    k_gemm<<<NROWS / 64, 256>>>(h, W, a);           // Wh + es/ed/exp tables
    k_adjbits<<<(NN * 16) / 256, 256>>>(adj);       // adj bitmask
    k_attn<<<BT * 8, 256, attn_smem>>>(out);        // fused softmax-attention
}

// round 9
// speedup vs baseline: 1.4839x; 1.2808x over previous
#include <cuda_runtime.h>
#include <cuda_bf16.h>
#include <cstdint>

// Problem constants: B=4, T=32 -> BT=128 slices; N=512 nodes; F_in=D=128.
#define BT    128
#define NN    512
#define DD    128
#define NROWS (BT * NN)       // 65536 total node-rows

typedef unsigned long long u64;
typedef unsigned int       u32;

// Scratch (allocation-free: __device__ globals)
__device__ float g_es[NROWS], g_ed[NROWS];
__device__ float g_F[NROWS], g_f[NROWS];           // exp(es), exp(0.2*es)
__device__ float g_G[NROWS], g_g[NROWS];           // exp(ed), exp(0.2*ed)
__device__ unsigned g_adjbits[NN * 16];            // bit j%32 of word [i][j/32]
// Wh transposed per slice, split into bf16 hi/lo: index [(bt*128 + d)*512 + j]
__device__ __align__(16) __nv_bfloat16 g_WhT_hi[NROWS * DD];
__device__ __align__(16) __nv_bfloat16 g_WhT_lo[NROWS * DD];

// ---- f32x2 helpers (k_gemm mainloop only) ----
__device__ __forceinline__ u64 pack2(float lo, float hi) {
    u64 r; asm("mov.b64 %0, {%1, %2};" : "=l"(r) : "f"(lo), "f"(hi)); return r;
}
__device__ __forceinline__ void ffma2(u64& d, u64 a, u64 b) {
    asm("fma.rn.f32x2 %0, %1, %2, %0;" : "+l"(d) : "l"(a), "l"(b));
}
__device__ __forceinline__ float2 unpack2(u64 v) {
    float2 f; asm("mov.b64 {%0, %1}, %2;" : "=f"(f.x), "=f"(f.y) : "l"(v)); return f;
}

__device__ __forceinline__ u32 smem_u32(const void* p) {
    u32 a;
    asm("{ .reg .u64 t; cvta.to.shared.u64 t, %1; cvt.u32.u64 %0, t; }"
        : "=r"(a) : "l"(p));
    return a;
}

// ---- family-portable tensor ops: ldmatrix + mma.sync (bf16, f32 acc) ----
#define LDSM4(r, addr) \
    asm volatile("ldmatrix.sync.aligned.m8n8.x4.shared.b16 {%0,%1,%2,%3}, [%4];" \
        : "=r"((r)[0]), "=r"((r)[1]), "=r"((r)[2]), "=r"((r)[3]) : "r"(addr))

__device__ __forceinline__ void mma_bf16(float* d, const u32* a, const u32* b) {
    asm volatile("mma.sync.aligned.m16n8k16.row.col.f32.bf16.bf16.f32 "
        "{%0,%1,%2,%3}, {%4,%5,%6,%7}, {%8,%9}, {%0,%1,%2,%3};"
        : "+f"(d[0]), "+f"(d[1]), "+f"(d[2]), "+f"(d[3])
        : "r"(a[0]), "r"(a[1]), "r"(a[2]), "r"(a[3]), "r"(b[0]), "r"(b[1]));
}

// ---------------------------------------------------------------------------
// Kernel 1: Wh = h @ W  (M=65536, K=128, N=128), tile 64x128.
// Epilogue: es/ed dot products + exp tables + TRANSPOSED bf16 hi/lo Wh store.
// ---------------------------------------------------------------------------
__global__ __launch_bounds__(256) void k_gemm(const float* __restrict__ h,
                                              const float* __restrict__ W,
                                              const float* __restrict__ a) {
    __shared__ float hs[64][33];
    __shared__ float Ws[32][128];
    __shared__ float sred[64][17];
    __shared__ float dred[64][17];

    const int row0 = blockIdx.x * 64;
    const int tid  = threadIdx.x;
    const int tx   = tid & 15;
    const int ty   = tid >> 4;

    u64 acc2[4][4];
#pragma unroll
    for (int r = 0; r < 4; r++)
#pragma unroll
        for (int d = 0; d < 4; d++) acc2[r][d] = 0ull;

    for (int k0 = 0; k0 < 128; k0 += 32) {
        __syncthreads();
#pragma unroll
        for (int l = 0; l < 2; l++) {
            int idx = tid + l * 256;
            int r = idx >> 3, c4 = (idx & 7) * 4;
            float4 v = *(const float4*)&h[(size_t)(row0 + r) * 128 + k0 + c4];
            hs[r][c4 + 0] = v.x; hs[r][c4 + 1] = v.y;
            hs[r][c4 + 2] = v.z; hs[r][c4 + 3] = v.w;
        }
#pragma unroll
        for (int l = 0; l < 4; l++) {
            int idx = tid + l * 256;
            int kk = idx >> 5, dc = (idx & 31) * 4;
            *(float4*)&Ws[kk][dc] = *(const float4*)&W[(k0 + kk) * 128 + dc];
        }
        __syncthreads();
#pragma unroll 8
        for (int k = 0; k < 32; k++) {
            ulonglong2 wa = *(const ulonglong2*)&Ws[k][tx * 8];
            ulonglong2 wb = *(const ulonglong2*)&Ws[k][tx * 8 + 4];
#pragma unroll
            for (int r = 0; r < 4; r++) {
                float hv = hs[ty + r * 16][k];
                u64 h2 = pack2(hv, hv);
                ffma2(acc2[r][0], h2, wa.x);
                ffma2(acc2[r][1], h2, wa.y);
                ffma2(acc2[r][2], h2, wb.x);
                ffma2(acc2[r][3], h2, wb.y);
            }
        }
    }

    float a_s[8], a_d[8];
#pragma unroll
    for (int d = 0; d < 8; d++) {
        a_s[d] = a[tx * 8 + d];
        a_d[d] = a[128 + tx * 8 + d];
    }

#pragma unroll
    for (int r = 0; r < 4; r++) {
        int rl = ty + r * 16;
        int grow = row0 + rl;               // global node-row
        int bts = grow >> 9;                // bt slice
        int jj  = grow & 511;               // node within slice
        float v[8];
        float2 p;
        p = unpack2(acc2[r][0]); v[0] = p.x; v[1] = p.y;
        p = unpack2(acc2[r][1]); v[2] = p.x; v[3] = p.y;
        p = unpack2(acc2[r][2]); v[4] = p.x; v[5] = p.y;
        p = unpack2(acc2[r][3]); v[6] = p.x; v[7] = p.y;
        float s = 0.f, dd = 0.f;
#pragma unroll
        for (int d = 0; d < 8; d++) {
            s  += v[d] * a_s[d];
            dd += v[d] * a_d[d];
            size_t ti = ((size_t)bts * 128 + tx * 8 + d) * 512 + jj;
            __nv_bfloat16 hv = __float2bfloat16(v[d]);
            g_WhT_hi[ti] = hv;
            g_WhT_lo[ti] = __float2bfloat16(v[d] - __bfloat162float(hv));
        }
        sred[rl][tx] = s;
        dred[rl][tx] = dd;
    }
    __syncthreads();
    if (tid < 64) {
        float s = 0.f, dd = 0.f;
#pragma unroll
        for (int t = 0; t < 16; t++) { s += sred[tid][t]; dd += dred[tid][t]; }
        int n = row0 + tid;
        g_es[n] = s;  g_ed[n] = dd;
        g_F[n] = expf(s);         g_f[n] = expf(0.2f * s);
        g_G[n] = expf(dd);        g_g[n] = expf(0.2f * dd);
    }
}

// ---------------------------------------------------------------------------
// Kernel 2: adjacency -> bitmask
// ---------------------------------------------------------------------------
__global__ __launch_bounds__(256) void k_adjbits(const int* __restrict__ adj) {
    int idx = blockIdx.x * 256 + threadIdx.x;
    int i = idx >> 4, w = idx & 15;
    unsigned bits = 0;
#pragma unroll
    for (int b = 0; b < 32; b++)
        if (adj[i * NN + w * 32 + b] > 0) bits |= (1u << b);
    g_adjbits[idx] = bits;
}

// ---------------------------------------------------------------------------
// Kernel 3: tensor-core (mma.sync bf16) fused masked-softmax-attention.
// D[d][i] = sum_j WhT[d][j] * C[i][j];  out[i][d] = D[d][i] / den[i]
// A = WhT tile [128 d][64 j] (staged hi/lo), B = C tile [128 i][64 j]
// (built hi/lo by phase A). Both K-contiguous -> plain ldmatrix.x4 for A & B.
// Row pitch 72 bf16 (144 B: 16B-aligned, 4-bank skew -> conflict-free LDSM).
// Per warp: m16 (d = wp*16..+15) x n128 (all i) x k512, 3 split terms.
// ---------------------------------------------------------------------------
#define PITCH_B 144                      // 72 bf16 per row
__global__ __launch_bounds__(256) void k_attn(float* __restrict__ out) {
    extern __shared__ char dyn[];
    char* smA_hi = dyn;                  // [128][72] bf16 = 18432 B
    char* smA_lo = dyn + 18432;
    char* smB_hi = dyn + 36864;
    char* smB_lo = dyn + 55296;          // total 73728 B

    __shared__ unsigned bitsS[128 * 16];
    __shared__ float edS[64], GS[64], gS[64];
    __shared__ float denS[256];
    __shared__ float invD[128];

    const int tid  = threadIdx.x;
    const int lane = tid & 31;
    const int wp   = tid >> 5;
    const int bt   = blockIdx.x >> 2;
    const int tile = blockIdx.x & 3;
    const int base = bt * NN;
    const int i0   = tile * 128;

    // adjacency preload: 128 rows x 16 words (512 uint4, 2/thread)
#pragma unroll
    for (int l = 0; l < 2; l++) {
        int idx4 = tid + l * 256;
        int r = idx4 >> 2, w4 = (idx4 & 3) * 4;
        *(uint4*)&bitsS[r * 16 + w4] = *(const uint4*)&g_adjbits[(i0 + r) * 16 + w4];
    }

    // phase-A identity: thread owns C row i, j-half
    const int i    = tid >> 1;
    const int half = tid & 1;
    const float esv = g_es[base + i0 + i];
    const float Fv  = g_F[base + i0 + i];
    const float fv  = g_f[base + i0 + i];
    float den = 0.f;

    const __nv_bfloat16* srcHi = g_WhT_hi + (size_t)bt * 128 * 512;
    const __nv_bfloat16* srcLo = g_WhT_lo + (size_t)bt * 128 * 512;

    // ldmatrix lane->address maps
    const int arow  = (lane & 7) + ((lane >> 3) & 1) * 8;   // A: d row 0..15
    const int akoff = (lane >> 4) * 8;                      // A: k 0 or 8
    const int brow  = (lane & 7) + (lane >> 4) * 8;         // B: i row 0..15
    const int bkoff = ((lane >> 3) & 1) * 8;                // B: k 0 or 8
    const u32 adAhi = smem_u32(smA_hi) + (wp * 16 + arow) * PITCH_B + akoff * 2;
    const u32 adAlo = smem_u32(smA_lo) + (wp * 16 + arow) * PITCH_B + akoff * 2;
    const u32 adBhi = smem_u32(smB_hi) + brow * PITCH_B + bkoff * 2;
    const u32 adBlo = smem_u32(smB_lo) + brow * PITCH_B + bkoff * 2;

    float acc[16][4];
#pragma unroll
    for (int nf = 0; nf < 16; nf++)
#pragma unroll
        for (int q = 0; q < 4; q++) acc[nf][q] = 0.f;

    for (int ch = 0; ch < 8; ch++) {
        const int j0 = ch * 64;
        __syncthreads();                 // prior MMA reads done / bits ready
        // --- stage A tiles (WhT hi/lo) + exp tables ---
        if (tid < 64)       edS[tid]      = g_ed[base + j0 + tid];
        else if (tid < 128) GS[tid - 64]  = g_G[base + j0 + tid - 64];
        else if (tid < 192) gS[tid - 128] = g_g[base + j0 + tid - 128];
        {
            const int slot = tid & 7;            // 8 bf16 (16 B) each
            const int drow = tid >> 3;           // 32 d-rows per pass
#pragma unroll
            for (int it = 0; it < 4; it++) {
                int d = drow + it * 32;
                size_t off = (size_t)d * 512 + j0 + slot * 8;
                *(uint4*)(smA_hi + d * PITCH_B + slot * 16) = *(const uint4*)(srcHi + off);
                *(uint4*)(smA_lo + d * PITCH_B + slot * 16) = *(const uint4*)(srcLo + off);
            }
        }
        __syncthreads();
        // --- phase A: C tile row i, 32 j's (hi/lo bf16 pairs) ---
        {
            unsigned bits = bitsS[i * 16 + ch * 2 + half];
#pragma unroll
            for (int jj = 0; jj < 32; jj += 2) {
                int j = half * 32 + jj;
                float c0 = 0.f, c1 = 0.f;
                if ((bits >> jj) & 1u) {
                    float t = esv + edS[j];
                    c0 = (t > 0.f) ? Fv * GS[j] : fv * gS[j];
                }
                if ((bits >> (jj + 1)) & 1u) {
                    float t = esv + edS[j + 1];
                    c1 = (t > 0.f) ? Fv * GS[j + 1] : fv * gS[j + 1];
                }
                den += c0 + c1;
                __nv_bfloat162 hp = __floats2bfloat162_rn(c0, c1);
                float l0 = c0 - __bfloat162float(hp.x);
                float l1 = c1 - __bfloat162float(hp.y);
                __nv_bfloat162 lp = __floats2bfloat162_rn(l0, l1);
                *(u32*)(smB_hi + i * PITCH_B + j * 2) = *(u32*)&hp;
                *(u32*)(smB_lo + i * PITCH_B + j * 2) = *(u32*)&lp;
            }
        }
        __syncthreads();
        // --- MMA: 4 k-steps x 16 n-frags x {hh, hl, lh} ---
#pragma unroll
        for (int ks = 0; ks < 4; ks++) {
            u32 ahi[4], alo[4];
            LDSM4(ahi, adAhi + ks * 32);
            LDSM4(alo, adAlo + ks * 32);
#pragma unroll
            for (int p = 0; p < 8; p++) {        // pairs of n-frags (n16)
                u32 bhi[4], blo[4];
                LDSM4(bhi, adBhi + p * (16 * PITCH_B) + ks * 32);
                LDSM4(blo, adBlo + p * (16 * PITCH_B) + ks * 32);
                mma_bf16(acc[2 * p],     ahi, bhi);
                mma_bf16(acc[2 * p],     ahi, blo);
                mma_bf16(acc[2 * p],     alo, bhi);
                mma_bf16(acc[2 * p + 1], ahi, bhi + 2);
                mma_bf16(acc[2 * p + 1], ahi, blo + 2);
                mma_bf16(acc[2 * p + 1], alo, bhi + 2);
            }
        }
    }

    denS[tid] = den;
    __syncthreads();
    if (tid < 128) invD[tid] = 1.0f / (denS[2 * tid] + denS[2 * tid + 1]);
    __syncthreads();

    // epilogue: lane l frag nf -> D[d][i]: d = wp*16 + l/4 (+8), i = nf*8+2(l&3) (+1)
    {
        const int dl = wp * 16 + (lane >> 2);
        const int il = 2 * (lane & 3);
#pragma unroll
        for (int nf = 0; nf < 16; nf++) {
            int ir = nf * 8 + il;
            float v0 = invD[ir], v1 = invD[ir + 1];
            float* p0 = out + (size_t)(base + i0 + ir) * 128 + dl;
            p0[0]        = acc[nf][0] * v0;
            p0[128]      = acc[nf][1] * v1;
            p0[8]        = acc[nf][2] * v0;
            p0[128 + 8]  = acc[nf][3] * v1;
        }
    }
}

// ---------------------------------------------------------------------------
extern "C" void kernel_launch(void* const* d_in, const int* in_sizes, int n_in,
                              void* d_out, int out_size) {
    const float* h   = (const float*)d_in[0];   // (4,32,512,128) f32
    const int*   adj = (const int*)d_in[1];     // (512,512) i32
    const float* W   = (const float*)d_in[2];   // (128,128) f32
    const float* a   = (const float*)d_in[3];   // (256,) f32
    float* out = (float*)d_out;                 // (4,32,512,128) f32

    const int attn_smem = 4 * 128 * PITCH_B;    // 73728 B
    cudaFuncSetAttribute(k_attn, cudaFuncAttributeMaxDynamicSharedMemorySize,
                         attn_smem);

    k_gemm<<<NROWS / 64, 256>>>(h, W, a);       // Wh^T(bf16 hi/lo) + exp tables
    k_adjbits<<<(NN * 16) / 256, 256>>>(adj);   // adj bitmask
    k_attn<<<BT * 4, 256, attn_smem>>>(out);    // mma.sync softmax-attention
}

// round 10
// speedup vs baseline: 1.4891x; 1.0035x over previous
#include <cuda_runtime.h>
#include <cuda_bf16.h>
#include <cstdint>

// Problem constants: B=4, T=32 -> BT=128 slices; N=512 nodes; F_in=D=128.
#define BT    128
#define NN    512
#define DD    128
#define NROWS (BT * NN)       // 65536 total node-rows

typedef unsigned long long u64;
typedef unsigned int       u32;

// Scratch (allocation-free: __device__ globals)
__device__ float g_es[NROWS], g_ed[NROWS];
__device__ float g_F[NROWS], g_f[NROWS];           // exp(es), exp(0.2*es)
__device__ float g_G[NROWS], g_g[NROWS];           // exp(ed), exp(0.2*ed)
__device__ unsigned g_adjbits[NN * 16];            // bit j%32 of word [i][j/32]
// Wh transposed per slice, split into bf16 hi/lo: index [(bt*128 + d)*512 + j]
__device__ __align__(16) __nv_bfloat16 g_WhT_hi[NROWS * DD];
__device__ __align__(16) __nv_bfloat16 g_WhT_lo[NROWS * DD];

// ---- f32x2 helpers (k_gemm mainloop only) ----
__device__ __forceinline__ u64 pack2(float lo, float hi) {
    u64 r; asm("mov.b64 %0, {%1, %2};" : "=l"(r) : "f"(lo), "f"(hi)); return r;
}
__device__ __forceinline__ void ffma2(u64& d, u64 a, u64 b) {
    asm("fma.rn.f32x2 %0, %1, %2, %0;" : "+l"(d) : "l"(a), "l"(b));
}
__device__ __forceinline__ float2 unpack2(u64 v) {
    float2 f; asm("mov.b64 {%0, %1}, %2;" : "=f"(f.x), "=f"(f.y) : "l"(v)); return f;
}

__device__ __forceinline__ u32 smem_u32(const void* p) {
    u32 a;
    asm("{ .reg .u64 t; cvta.to.shared.u64 t, %1; cvt.u32.u64 %0, t; }"
        : "=r"(a) : "l"(p));
    return a;
}

// ---- family-portable tensor ops: ldmatrix + mma.sync (bf16, f32 acc) ----
#define LDSM4(r, addr) \
    asm volatile("ldmatrix.sync.aligned.m8n8.x4.shared.b16 {%0,%1,%2,%3}, [%4];" \
        : "=r"((r)[0]), "=r"((r)[1]), "=r"((r)[2]), "=r"((r)[3]) : "r"(addr))

__device__ __forceinline__ void mma_bf16(float* d, const u32* a, const u32* b) {
    asm volatile("mma.sync.aligned.m16n8k16.row.col.f32.bf16.bf16.f32 "
        "{%0,%1,%2,%3}, {%4,%5,%6,%7}, {%8,%9}, {%0,%1,%2,%3};"
        : "+f"(d[0]), "+f"(d[1]), "+f"(d[2]), "+f"(d[3])
        : "r"(a[0]), "r"(a[1]), "r"(a[2]), "r"(a[3]), "r"(b[0]), "r"(b[1]));
}

// ---------------------------------------------------------------------------
// Kernel 1: Wh = h @ W  (M=65536, K=128, N=128), tile 64x128.
// Epilogue: es/ed dot products + exp tables + TRANSPOSED bf16 hi/lo Wh store.
// ---------------------------------------------------------------------------
__global__ __launch_bounds__(256) void k_gemm(const float* __restrict__ h,
                                              const float* __restrict__ W,
                                              const float* __restrict__ a) {
    __shared__ float hs[64][33];
    __shared__ float Ws[32][128];
    __shared__ float sred[64][17];
    __shared__ float dred[64][17];

    const int row0 = blockIdx.x * 64;
    const int tid  = threadIdx.x;
    const int tx   = tid & 15;
    const int ty   = tid >> 4;

    u64 acc2[4][4];
#pragma unroll
    for (int r = 0; r < 4; r++)
#pragma unroll
        for (int d = 0; d < 4; d++) acc2[r][d] = 0ull;

    for (int k0 = 0; k0 < 128; k0 += 32) {
        __syncthreads();
#pragma unroll
        for (int l = 0; l < 2; l++) {
            int idx = tid + l * 256;
            int r = idx >> 3, c4 = (idx & 7) * 4;
            float4 v = *(const float4*)&h[(size_t)(row0 + r) * 128 + k0 + c4];
            hs[r][c4 + 0] = v.x; hs[r][c4 + 1] = v.y;
            hs[r][c4 + 2] = v.z; hs[r][c4 + 3] = v.w;
        }
#pragma unroll
        for (int l = 0; l < 4; l++) {
            int idx = tid + l * 256;
            int kk = idx >> 5, dc = (idx & 31) * 4;
            *(float4*)&Ws[kk][dc] = *(const float4*)&W[(k0 + kk) * 128 + dc];
        }
        __syncthreads();
#pragma unroll 8
        for (int k = 0; k < 32; k++) {
            ulonglong2 wa = *(const ulonglong2*)&Ws[k][tx * 8];
            ulonglong2 wb = *(const ulonglong2*)&Ws[k][tx * 8 + 4];
#pragma unroll
            for (int r = 0; r < 4; r++) {
                float hv = hs[ty + r * 16][k];
                u64 h2 = pack2(hv, hv);
                ffma2(acc2[r][0], h2, wa.x);
                ffma2(acc2[r][1], h2, wa.y);
                ffma2(acc2[r][2], h2, wb.x);
                ffma2(acc2[r][3], h2, wb.y);
            }
        }
    }

    float a_s[8], a_d[8];
#pragma unroll
    for (int d = 0; d < 8; d++) {
        a_s[d] = a[tx * 8 + d];
        a_d[d] = a[128 + tx * 8 + d];
    }

#pragma unroll
    for (int r = 0; r < 4; r++) {
        int rl = ty + r * 16;
        int grow = row0 + rl;               // global node-row
        int bts = grow >> 9;                // bt slice
        int jj  = grow & 511;               // node within slice
        float v[8];
        float2 p;
        p = unpack2(acc2[r][0]); v[0] = p.x; v[1] = p.y;
        p = unpack2(acc2[r][1]); v[2] = p.x; v[3] = p.y;
        p = unpack2(acc2[r][2]); v[4] = p.x; v[5] = p.y;
        p = unpack2(acc2[r][3]); v[6] = p.x; v[7] = p.y;
        float s = 0.f, dd = 0.f;
#pragma unroll
        for (int d = 0; d < 8; d++) {
            s  += v[d] * a_s[d];
            dd += v[d] * a_d[d];
            size_t ti = ((size_t)bts * 128 + tx * 8 + d) * 512 + jj;
            __nv_bfloat16 hv = __float2bfloat16(v[d]);
            g_WhT_hi[ti] = hv;
            g_WhT_lo[ti] = __float2bfloat16(v[d] - __bfloat162float(hv));
        }
        sred[rl][tx] = s;
        dred[rl][tx] = dd;
    }
    __syncthreads();
    if (tid < 64) {
        float s = 0.f, dd = 0.f;
#pragma unroll
        for (int t = 0; t < 16; t++) { s += sred[tid][t]; dd += dred[tid][t]; }
        int n = row0 + tid;
        g_es[n] = s;  g_ed[n] = dd;
        g_F[n] = expf(s);         g_f[n] = expf(0.2f * s);
        g_G[n] = expf(dd);        g_g[n] = expf(0.2f * dd);
    }
}

// ---------------------------------------------------------------------------
// Kernel 2: adjacency -> bitmask
// ---------------------------------------------------------------------------
__global__ __launch_bounds__(256) void k_adjbits(const int* __restrict__ adj) {
    int idx = blockIdx.x * 256 + threadIdx.x;
    int i = idx >> 4, w = idx & 15;
    unsigned bits = 0;
#pragma unroll
    for (int b = 0; b < 32; b++)
        if (adj[i * NN + w * 32 + b] > 0) bits |= (1u << b);
    g_adjbits[idx] = bits;
}

// ---------------------------------------------------------------------------
// Kernel 3: tensor-core (mma.sync bf16) fused masked-softmax-attention.
// D[d][i] = sum_j WhT[d][j] * C[i][j];  out[i][d] = D[d][i] / den[i]
// A = WhT tile [128 d][64 j] (staged hi/lo), B = C tile [128 i][64 j]
// (built hi/lo by phase A). Both K-contiguous -> plain ldmatrix.x4 for A & B.
// Row pitch 72 bf16 (144 B: 16B-aligned, 4-bank skew -> conflict-free LDSM).
// Per warp: m16 (d = wp*16..+15) x n128 (all i) x k512, 3 split terms.
// ---------------------------------------------------------------------------
#define PITCH_B 144                      // 72 bf16 per row
__global__ __launch_bounds__(256) void k_attn(float* __restrict__ out) {
    extern __shared__ char dyn[];
    char* smA_hi = dyn;                  // [128][72] bf16 = 18432 B
    char* smA_lo = dyn + 18432;
    char* smB_hi = dyn + 36864;
    char* smB_lo = dyn + 55296;          // total 73728 B

    __shared__ unsigned bitsS[128 * 16];
    __shared__ float edS[64], GS[64], gS[64];
    __shared__ float denS[256];
    __shared__ float invD[128];

    const int tid  = threadIdx.x;
    const int lane = tid & 31;
    const int wp   = tid >> 5;
    const int bt   = blockIdx.x >> 2;
    const int tile = blockIdx.x & 3;
    const int base = bt * NN;
    const int i0   = tile * 128;

    // adjacency preload: 128 rows x 16 words (512 uint4, 2/thread)
#pragma unroll
    for (int l = 0; l < 2; l++) {
        int idx4 = tid + l * 256;
        int r = idx4 >> 2, w4 = (idx4 & 3) * 4;
        *(uint4*)&bitsS[r * 16 + w4] = *(const uint4*)&g_adjbits[(i0 + r) * 16 + w4];
    }

    // phase-A identity: thread owns C row i, j-half
    const int i    = tid >> 1;
    const int half = tid & 1;
    const float esv = g_es[base + i0 + i];
    const float Fv  = g_F[base + i0 + i];
    const float fv  = g_f[base + i0 + i];
    float den = 0.f;

    const __nv_bfloat16* srcHi = g_WhT_hi + (size_t)bt * 128 * 512;
    const __nv_bfloat16* srcLo = g_WhT_lo + (size_t)bt * 128 * 512;

    // ldmatrix lane->address maps
    const int arow  = (lane & 7) + ((lane >> 3) & 1) * 8;   // A: d row 0..15
    const int akoff = (lane >> 4) * 8;                      // A: k 0 or 8
    const int brow  = (lane & 7) + (lane >> 4) * 8;         // B: i row 0..15
    const int bkoff = ((lane >> 3) & 1) * 8;                // B: k 0 or 8
    const u32 adAhi = smem_u32(smA_hi) + (wp * 16 + arow) * PITCH_B + akoff * 2;
    const u32 adAlo = smem_u32(smA_lo) + (wp * 16 + arow) * PITCH_B + akoff * 2;
    const u32 adBhi = smem_u32(smB_hi) + brow * PITCH_B + bkoff * 2;
    const u32 adBlo = smem_u32(smB_lo) + brow * PITCH_B + bkoff * 2;

    float acc[16][4];
#pragma unroll
    for (int nf = 0; nf < 16; nf++)
#pragma unroll
        for (int q = 0; q < 4; q++) acc[nf][q] = 0.f;

    for (int ch = 0; ch < 8; ch++) {
        const int j0 = ch * 64;
        __syncthreads();                 // prior MMA reads done / bits ready
        // --- stage A tiles (WhT hi/lo) + exp tables ---
        if (tid < 64)       edS[tid]      = g_ed[base + j0 + tid];
        else if (tid < 128) GS[tid - 64]  = g_G[base + j0 + tid - 64];
        else if (tid < 192) gS[tid - 128] = g_g[base + j0 + tid - 128];
        {
            const int slot = tid & 7;            // 8 bf16 (16 B) each
            const int drow = tid >> 3;           // 32 d-rows per pass
#pragma unroll
            for (int it = 0; it < 4; it++) {
                int d = drow + it * 32;
                size_t off = (size_t)d * 512 + j0 + slot * 8;
                *(uint4*)(smA_hi + d * PITCH_B + slot * 16) = *(const uint4*)(srcHi + off);
                *(uint4*)(smA_lo + d * PITCH_B + slot * 16) = *(const uint4*)(srcLo + off);
            }
        }
        __syncthreads();
        // --- phase A: C tile row i, 32 j's (hi/lo bf16 pairs) ---
        {
            unsigned bits = bitsS[i * 16 + ch * 2 + half];
#pragma unroll
            for (int jj = 0; jj < 32; jj += 2) {
                int j = half * 32 + jj;
                float c0 = 0.f, c1 = 0.f;
                if ((bits >> jj) & 1u) {
                    float t = esv + edS[j];
                    c0 = (t > 0.f) ? Fv * GS[j] : fv * gS[j];
                }
                if ((bits >> (jj + 1)) & 1u) {
                    float t = esv + edS[j + 1];
                    c1 = (t > 0.f) ? Fv * GS[j + 1] : fv * gS[j + 1];
                }
                den += c0 + c1;
                __nv_bfloat162 hp = __floats2bfloat162_rn(c0, c1);
                float l0 = c0 - __bfloat162float(hp.x);
                float l1 = c1 - __bfloat162float(hp.y);
                __nv_bfloat162 lp = __floats2bfloat162_rn(l0, l1);
                *(u32*)(smB_hi + i * PITCH_B + j * 2) = *(u32*)&hp;
                *(u32*)(smB_lo + i * PITCH_B + j * 2) = *(u32*)&lp;
            }
        }
        __syncthreads();
        // --- MMA: 4 k-steps x 16 n-frags x {hh, hl, lh} ---
#pragma unroll
        for (int ks = 0; ks < 4; ks++) {
            u32 ahi[4], alo[4];
            LDSM4(ahi, adAhi + ks * 32);
            LDSM4(alo, adAlo + ks * 32);
#pragma unroll
            for (int p = 0; p < 8; p++) {        // pairs of n-frags (n16)
                u32 bhi[4], blo[4];
                LDSM4(bhi, adBhi + p * (16 * PITCH_B) + ks * 32);
                LDSM4(blo, adBlo + p * (16 * PITCH_B) + ks * 32);
                mma_bf16(acc[2 * p],     ahi, bhi);
                mma_bf16(acc[2 * p],     ahi, blo);
                mma_bf16(acc[2 * p],     alo, bhi);
                mma_bf16(acc[2 * p + 1], ahi, bhi + 2);
                mma_bf16(acc[2 * p + 1], ahi, blo + 2);
                mma_bf16(acc[2 * p + 1], alo, bhi + 2);
            }
        }
    }

    denS[tid] = den;
    __syncthreads();
    if (tid < 128) invD[tid] = 1.0f / (denS[2 * tid] + denS[2 * tid + 1]);
    __syncthreads();

    // epilogue: lane l frag nf -> D[d][i]: d = wp*16 + l/4 (+8), i = nf*8+2(l&3) (+1)
    {
        const int dl = wp * 16 + (lane >> 2);
        const int il = 2 * (lane & 3);
#pragma unroll
        for (int nf = 0; nf < 16; nf++) {
            int ir = nf * 8 + il;
            float v0 = invD[ir], v1 = invD[ir + 1];
            float* p0 = out + (size_t)(base + i0 + ir) * 128 + dl;
            p0[0]        = acc[nf][0] * v0;
            p0[128]      = acc[nf][1] * v1;
            p0[8]        = acc[nf][2] * v0;
            p0[128 + 8]  = acc[nf][3] * v1;
        }
    }
}

// ---------------------------------------------------------------------------
extern "C" void kernel_launch(void* const* d_in, const int* in_sizes, int n_in,
                              void* d_out, int out_size) {
    const float* h   = (const float*)d_in[0];   // (4,32,512,128) f32
    const int*   adj = (const int*)d_in[1];     // (512,512) i32
    const float* W   = (const float*)d_in[2];   // (128,128) f32
    const float* a   = (const float*)d_in[3];   // (256,) f32
    float* out = (float*)d_out;                 // (4,32,512,128) f32

    const int attn_smem = 4 * 128 * PITCH_B;    // 73728 B
    cudaFuncSetAttribute(k_attn, cudaFuncAttributeMaxDynamicSharedMemorySize,
                         attn_smem);

    k_gemm<<<NROWS / 64, 256>>>(h, W, a);       // Wh^T(bf16 hi/lo) + exp tables
    k_adjbits<<<(NN * 16) / 256, 256>>>(adj);   // adj bitmask
    k_attn<<<BT * 4, 256, attn_smem>>>(out);    // mma.sync softmax-attention
}

// round 11
// speedup vs baseline: 1.6839x; 1.1308x over previous
#include <cuda_runtime.h>
#include <cuda_bf16.h>
#include <cstdint>

// Problem constants: B=4, T=32 -> BT=128 slices; N=512 nodes; F_in=D=128.
#define BT    128
#define NN    512
#define DD    128
#define NROWS (BT * NN)       // 65536 total node-rows

typedef unsigned long long u64;
typedef unsigned int       u32;
typedef unsigned short     u16;

// Scratch (allocation-free: __device__ globals)
__device__ float g_es[NROWS], g_ed[NROWS];
__device__ float g_F[NROWS], g_f[NROWS];           // exp(es), exp(0.2*es)
__device__ float g_G[NROWS], g_g[NROWS];           // exp(ed), exp(0.2*ed)
__device__ unsigned g_adjbits[NN * 16];            // bit j%32 of word [i][j/32]
// Wh transposed per slice, split into bf16 hi/lo: index [(bt*128 + d)*512 + j]
__device__ __align__(16) __nv_bfloat16 g_WhT_hi[NROWS * DD];
__device__ __align__(16) __nv_bfloat16 g_WhT_lo[NROWS * DD];

// ---- f32x2 helpers (k_gemm mainloop only) ----
__device__ __forceinline__ u64 pack2(float lo, float hi) {
    u64 r; asm("mov.b64 %0, {%1, %2};" : "=l"(r) : "f"(lo), "f"(hi)); return r;
}
__device__ __forceinline__ void ffma2(u64& d, u64 a, u64 b) {
    asm("fma.rn.f32x2 %0, %1, %2, %0;" : "+l"(d) : "l"(a), "l"(b));
}
__device__ __forceinline__ float2 unpack2(u64 v) {
    float2 f; asm("mov.b64 {%0, %1}, %2;" : "=f"(f.x), "=f"(f.y) : "l"(v)); return f;
}

__device__ __forceinline__ u32 smem_u32(const void* p) {
    u32 a;
    asm("{ .reg .u64 t; cvta.to.shared.u64 t, %1; cvt.u32.u64 %0, t; }"
        : "=r"(a) : "l"(p));
    return a;
}

// ---- family-portable tensor ops: ldmatrix + mma.sync (bf16, f32 acc) ----
#define LDSM4(r, addr) \
    asm volatile("ldmatrix.sync.aligned.m8n8.x4.shared.b16 {%0,%1,%2,%3}, [%4];" \
        : "=r"((r)[0]), "=r"((r)[1]), "=r"((r)[2]), "=r"((r)[3]) : "r"(addr))

__device__ __forceinline__ void mma_bf16(float* d, const u32* a, const u32* b) {
    asm volatile("mma.sync.aligned.m16n8k16.row.col.f32.bf16.bf16.f32 "
        "{%0,%1,%2,%3}, {%4,%5,%6,%7}, {%8,%9}, {%0,%1,%2,%3};"
        : "+f"(d[0]), "+f"(d[1]), "+f"(d[2]), "+f"(d[3])
        : "r"(a[0]), "r"(a[1]), "r"(a[2]), "r"(a[3]), "r"(b[0]), "r"(b[1]));
}

// ---------------------------------------------------------------------------
// Kernel 1: Wh = h @ W  (M=65536, K=128, N=128), tile 64x128.
// Epilogue: es/ed dot products + exp tables + smem-staged TRANSPOSED bf16
// hi/lo Wh store (coalesced STG.128 instead of scattered STG.16).
// ---------------------------------------------------------------------------
#define TBP 130                          // transpose buffer pitch (bf16), odd u32
__global__ __launch_bounds__(256) void k_gemm(const float* __restrict__ h,
                                              const float* __restrict__ W,
                                              const float* __restrict__ a) {
    __shared__ union {
        struct { float hs[64][33]; float Ws[32][128]; } mm;   // 24832 B
        __nv_bfloat16 tb[2][64 * TBP];                        // 33280 B
    } sm;
    __shared__ float sred[64][17];
    __shared__ float dred[64][17];

    const int row0 = blockIdx.x * 64;
    const int tid  = threadIdx.x;
    const int tx   = tid & 15;
    const int ty   = tid >> 4;

    u64 acc2[4][4];
#pragma unroll
    for (int r = 0; r < 4; r++)
#pragma unroll
        for (int d = 0; d < 4; d++) acc2[r][d] = 0ull;

    for (int k0 = 0; k0 < 128; k0 += 32) {
        __syncthreads();
#pragma unroll
        for (int l = 0; l < 2; l++) {
            int idx = tid + l * 256;
            int r = idx >> 3, c4 = (idx & 7) * 4;
            float4 v = *(const float4*)&h[(size_t)(row0 + r) * 128 + k0 + c4];
            sm.mm.hs[r][c4 + 0] = v.x; sm.mm.hs[r][c4 + 1] = v.y;
            sm.mm.hs[r][c4 + 2] = v.z; sm.mm.hs[r][c4 + 3] = v.w;
        }
#pragma unroll
        for (int l = 0; l < 4; l++) {
            int idx = tid + l * 256;
            int kk = idx >> 5, dc = (idx & 31) * 4;
            *(float4*)&sm.mm.Ws[kk][dc] = *(const float4*)&W[(k0 + kk) * 128 + dc];
        }
        __syncthreads();
#pragma unroll 8
        for (int k = 0; k < 32; k++) {
            ulonglong2 wa = *(const ulonglong2*)&sm.mm.Ws[k][tx * 8];
            ulonglong2 wb = *(const ulonglong2*)&sm.mm.Ws[k][tx * 8 + 4];
#pragma unroll
            for (int r = 0; r < 4; r++) {
                float hv = sm.mm.hs[ty + r * 16][k];
                u64 h2 = pack2(hv, hv);
                ffma2(acc2[r][0], h2, wa.x);
                ffma2(acc2[r][1], h2, wa.y);
                ffma2(acc2[r][2], h2, wb.x);
                ffma2(acc2[r][3], h2, wb.y);
            }
        }
    }
    __syncthreads();   // mainloop reads of hs/Ws done before tb overwrite

    float a_s[8], a_d[8];
#pragma unroll
    for (int d = 0; d < 8; d++) {
        a_s[d] = a[tx * 8 + d];
        a_d[d] = a[128 + tx * 8 + d];
    }

#pragma unroll
    for (int r = 0; r < 4; r++) {
        int rl = ty + r * 16;              // local j (0..63)
        float v[8];
        float2 p;
        p = unpack2(acc2[r][0]); v[0] = p.x; v[1] = p.y;
        p = unpack2(acc2[r][1]); v[2] = p.x; v[3] = p.y;
        p = unpack2(acc2[r][2]); v[4] = p.x; v[5] = p.y;
        p = unpack2(acc2[r][3]); v[6] = p.x; v[7] = p.y;
        float s = 0.f, dd = 0.f;
#pragma unroll
        for (int d = 0; d < 8; d += 2) {
            s  += v[d] * a_s[d]     + v[d + 1] * a_s[d + 1];
            dd += v[d] * a_d[d]     + v[d + 1] * a_d[d + 1];
            __nv_bfloat162 hp = __floats2bfloat162_rn(v[d], v[d + 1]);
            float l0 = v[d]     - __bfloat162float(hp.x);
            float l1 = v[d + 1] - __bfloat162float(hp.y);
            __nv_bfloat162 lp = __floats2bfloat162_rn(l0, l1);
            *(u32*)&sm.tb[0][rl * TBP + tx * 8 + d] = *(u32*)&hp;
            *(u32*)&sm.tb[1][rl * TBP + tx * 8 + d] = *(u32*)&lp;
        }
        sred[rl][tx] = s;
        dred[rl][tx] = dd;
    }
    __syncthreads();

    // es/ed reduction + exp tables
    if (tid < 64) {
        float s = 0.f, dd = 0.f;
#pragma unroll
        for (int t = 0; t < 16; t++) { s += sred[tid][t]; dd += dred[tid][t]; }
        int n = row0 + tid;
        g_es[n] = s;  g_ed[n] = dd;
        g_F[n] = expf(s);         g_f[n] = expf(0.2f * s);
        g_G[n] = expf(dd);        g_g[n] = expf(0.2f * dd);
    }

    // transposed coalesced store: thread = d-row (tid>>1), j-half (tid&1)
    {
        const int bts   = row0 >> 9;
        const int jcol0 = row0 & 511;
        const int dr    = tid >> 1;
        const int jb    = (tid & 1) * 32;
        size_t gbase = ((size_t)bts * 128 + dr) * 512 + jcol0 + jb;
#pragma unroll
        for (int buf = 0; buf < 2; buf++) {
            __nv_bfloat16* gdst = buf ? g_WhT_lo : g_WhT_hi;
            const __nv_bfloat16* src = sm.tb[buf];
#pragma unroll
            for (int q = 0; q < 4; q++) {
                u16 w[8];
#pragma unroll
                for (int e = 0; e < 8; e++)
                    w[e] = *(const u16*)&src[(jb + q * 8 + e) * TBP + dr];
                *(uint4*)&gdst[gbase + q * 8] = *(uint4*)w;
            }
        }
    }
}

// ---------------------------------------------------------------------------
// Kernel 2: adjacency -> bitmask
// ---------------------------------------------------------------------------
__global__ __launch_bounds__(256) void k_adjbits(const int* __restrict__ adj) {
    int idx = blockIdx.x * 256 + threadIdx.x;
    int i = idx >> 4, w = idx & 15;
    unsigned bits = 0;
#pragma unroll
    for (int b = 0; b < 32; b++)
        if (adj[i * NN + w * 32 + b] > 0) bits |= (1u << b);
    g_adjbits[idx] = bits;
}

// ---------------------------------------------------------------------------
// Kernel 3: tensor-core (mma.sync bf16) fused masked-softmax-attention.
// D[d][i] = sum_j WhT[d][j] * C[i][j];  out[i][d] = D[d][i] / den[i]
// (unchanged from R10 passing version)
// ---------------------------------------------------------------------------
#define PITCH_B 144                      // 72 bf16 per row
__global__ __launch_bounds__(256) void k_attn(float* __restrict__ out) {
    extern __shared__ char dyn[];
    char* smA_hi = dyn;                  // [128][72] bf16 = 18432 B
    char* smA_lo = dyn + 18432;
    char* smB_hi = dyn + 36864;
    char* smB_lo = dyn + 55296;          // total 73728 B

    __shared__ unsigned bitsS[128 * 16];
    __shared__ float edS[64], GS[64], gS[64];
    __shared__ float denS[256];
    __shared__ float invD[128];

    const int tid  = threadIdx.x;
    const int lane = tid & 31;
    const int wp   = tid >> 5;
    const int bt   = blockIdx.x >> 2;
    const int tile = blockIdx.x & 3;
    const int base = bt * NN;
    const int i0   = tile * 128;

#pragma unroll
    for (int l = 0; l < 2; l++) {
        int idx4 = tid + l * 256;
        int r = idx4 >> 2, w4 = (idx4 & 3) * 4;
        *(uint4*)&bitsS[r * 16 + w4] = *(const uint4*)&g_adjbits[(i0 + r) * 16 + w4];
    }

    const int i    = tid >> 1;
    const int half = tid & 1;
    const float esv = g_es[base + i0 + i];
    const float Fv  = g_F[base + i0 + i];
    const float fv  = g_f[base + i0 + i];
    float den = 0.f;

    const __nv_bfloat16* srcHi = g_WhT_hi + (size_t)bt * 128 * 512;
    const __nv_bfloat16* srcLo = g_WhT_lo + (size_t)bt * 128 * 512;

    const int arow  = (lane & 7) + ((lane >> 3) & 1) * 8;
    const int akoff = (lane >> 4) * 8;
    const int brow  = (lane & 7) + (lane >> 4) * 8;
    const int bkoff = ((lane >> 3) & 1) * 8;
    const u32 adAhi = smem_u32(smA_hi) + (wp * 16 + arow) * PITCH_B + akoff * 2;
    const u32 adAlo = smem_u32(smA_lo) + (wp * 16 + arow) * PITCH_B + akoff * 2;
    const u32 adBhi = smem_u32(smB_hi) + brow * PITCH_B + bkoff * 2;
    const u32 adBlo = smem_u32(smB_lo) + brow * PITCH_B + bkoff * 2;

    float acc[16][4];
#pragma unroll
    for (int nf = 0; nf < 16; nf++)
#pragma unroll
        for (int q = 0; q < 4; q++) acc[nf][q] = 0.f;

    for (int ch = 0; ch < 8; ch++) {
        const int j0 = ch * 64;
        __syncthreads();
        if (tid < 64)       edS[tid]      = g_ed[base + j0 + tid];
        else if (tid < 128) GS[tid - 64]  = g_G[base + j0 + tid - 64];
        else if (tid < 192) gS[tid - 128] = g_g[base + j0 + tid - 128];
        {
            const int slot = tid & 7;
            const int drow = tid >> 3;
#pragma unroll
            for (int it = 0; it < 4; it++) {
                int d = drow + it * 32;
                size_t off = (size_t)d * 512 + j0 + slot * 8;
                *(uint4*)(smA_hi + d * PITCH_B + slot * 16) = *(const uint4*)(srcHi + off);
                *(uint4*)(smA_lo + d * PITCH_B + slot * 16) = *(const uint4*)(srcLo + off);
            }
        }
        __syncthreads();
        {
            unsigned bits = bitsS[i * 16 + ch * 2 + half];
#pragma unroll
            for (int jj = 0; jj < 32; jj += 2) {
                int j = half * 32 + jj;
                float c0 = 0.f, c1 = 0.f;
                if ((bits >> jj) & 1u) {
                    float t = esv + edS[j];
                    c0 = (t > 0.f) ? Fv * GS[j] : fv * gS[j];
                }
                if ((bits >> (jj + 1)) & 1u) {
                    float t = esv + edS[j + 1];
                    c1 = (t > 0.f) ? Fv * GS[j + 1] : fv * gS[j + 1];
                }
                den += c0 + c1;
                __nv_bfloat162 hp = __floats2bfloat162_rn(c0, c1);
                float l0 = c0 - __bfloat162float(hp.x);
                float l1 = c1 - __bfloat162float(hp.y);
                __nv_bfloat162 lp = __floats2bfloat162_rn(l0, l1);
                *(u32*)(smB_hi + i * PITCH_B + j * 2) = *(u32*)&hp;
                *(u32*)(smB_lo + i * PITCH_B + j * 2) = *(u32*)&lp;
            }
        }
        __syncthreads();
#pragma unroll
        for (int ks = 0; ks < 4; ks++) {
            u32 ahi[4], alo[4];
            LDSM4(ahi, adAhi + ks * 32);
            LDSM4(alo, adAlo + ks * 32);
#pragma unroll
            for (int p = 0; p < 8; p++) {
                u32 bhi[4], blo[4];
                LDSM4(bhi, adBhi + p * (16 * PITCH_B) + ks * 32);
                LDSM4(blo, adBlo + p * (16 * PITCH_B) + ks * 32);
                mma_bf16(acc[2 * p],     ahi, bhi);
                mma_bf16(acc[2 * p],     ahi, blo);
                mma_bf16(acc[2 * p],     alo, bhi);
                mma_bf16(acc[2 * p + 1], ahi, bhi + 2);
                mma_bf16(acc[2 * p + 1], ahi, blo + 2);
                mma_bf16(acc[2 * p + 1], alo, bhi + 2);
            }
        }
    }

    denS[tid] = den;
    __syncthreads();
    if (tid < 128) invD[tid] = 1.0f / (denS[2 * tid] + denS[2 * tid + 1]);
    __syncthreads();

    {
        const int dl = wp * 16 + (lane >> 2);
        const int il = 2 * (lane & 3);
#pragma unroll
        for (int nf = 0; nf < 16; nf++) {
            int ir = nf * 8 + il;
            float v0 = invD[ir], v1 = invD[ir + 1];
            float* p0 = out + (size_t)(base + i0 + ir) * 128 + dl;
            p0[0]        = acc[nf][0] * v0;
            p0[128]      = acc[nf][1] * v1;
            p0[8]        = acc[nf][2] * v0;
            p0[128 + 8]  = acc[nf][3] * v1;
        }
    }
}

// ---------------------------------------------------------------------------
extern "C" void kernel_launch(void* const* d_in, const int* in_sizes, int n_in,
                              void* d_out, int out_size) {
    const float* h   = (const float*)d_in[0];   // (4,32,512,128) f32
    const int*   adj = (const int*)d_in[1];     // (512,512) i32
    const float* W   = (const float*)d_in[2];   // (128,128) f32
    const float* a   = (const float*)d_in[3];   // (256,) f32
    float* out = (float*)d_out;                 // (4,32,512,128) f32

    const int attn_smem = 4 * 128 * PITCH_B;    // 73728 B
    cudaFuncSetAttribute(k_attn, cudaFuncAttributeMaxDynamicSharedMemorySize,
                         attn_smem);

    k_gemm<<<NROWS / 64, 256>>>(h, W, a);       // Wh^T(bf16 hi/lo) + exp tables
    k_adjbits<<<(NN * 16) / 256, 256>>>(adj);   // adj bitmask
    k_attn<<<BT * 4, 256, attn_smem>>>(out);    // mma.sync softmax-attention
}

// round 12
// speedup vs baseline: 1.6904x; 1.0039x over previous
#include <cuda_runtime.h>
#include <cuda_bf16.h>
#include <cstdint>

// Problem constants: B=4, T=32 -> BT=128 slices; N=512 nodes; F_in=D=128.
#define BT    128
#define NN    512
#define DD    128
#define NROWS (BT * NN)       // 65536 total node-rows

typedef unsigned long long u64;
typedef unsigned int       u32;
typedef unsigned short     u16;

// Scratch (allocation-free: __device__ globals)
__device__ float g_es[NROWS], g_ed[NROWS];
__device__ float g_F[NROWS], g_f[NROWS];           // exp(es), exp(0.2*es)
__device__ float g_G[NROWS], g_g[NROWS];           // exp(ed), exp(0.2*ed)
__device__ unsigned g_adjbits[NN * 16];            // bit j%32 of word [i][j/32]
// Wh transposed per slice, split into bf16 hi/lo: index [(bt*128 + d)*512 + j]
__device__ __align__(16) __nv_bfloat16 g_WhT_hi[NROWS * DD];
__device__ __align__(16) __nv_bfloat16 g_WhT_lo[NROWS * DD];

// ---- f32x2 helpers (k_gemm mainloop only) ----
__device__ __forceinline__ u64 pack2(float lo, float hi) {
    u64 r; asm("mov.b64 %0, {%1, %2};" : "=l"(r) : "f"(lo), "f"(hi)); return r;
}
__device__ __forceinline__ void ffma2(u64& d, u64 a, u64 b) {
    asm("fma.rn.f32x2 %0, %1, %2, %0;" : "+l"(d) : "l"(a), "l"(b));
}
__device__ __forceinline__ float2 unpack2(u64 v) {
    float2 f; asm("mov.b64 {%0, %1}, %2;" : "=f"(f.x), "=f"(f.y) : "l"(v)); return f;
}

__device__ __forceinline__ u32 smem_u32(const void* p) {
    u32 a;
    asm("{ .reg .u64 t; cvta.to.shared.u64 t, %1; cvt.u32.u64 %0, t; }"
        : "=r"(a) : "l"(p));
    return a;
}

// ---- family-portable tensor ops: ldmatrix + mma.sync (bf16, f32 acc) ----
#define LDSM4(r, addr) \
    asm volatile("ldmatrix.sync.aligned.m8n8.x4.shared.b16 {%0,%1,%2,%3}, [%4];" \
        : "=r"((r)[0]), "=r"((r)[1]), "=r"((r)[2]), "=r"((r)[3]) : "r"(addr))

__device__ __forceinline__ void mma_bf16(float* d, const u32* a, const u32* b) {
    asm volatile("mma.sync.aligned.m16n8k16.row.col.f32.bf16.bf16.f32 "
        "{%0,%1,%2,%3}, {%4,%5,%6,%7}, {%8,%9}, {%0,%1,%2,%3};"
        : "+f"(d[0]), "+f"(d[1]), "+f"(d[2]), "+f"(d[3])
        : "r"(a[0]), "r"(a[1]), "r"(a[2]), "r"(a[3]), "r"(b[0]), "r"(b[1]));
}

// ---------------------------------------------------------------------------
// Kernel 1: Wh = h @ W  (M=65536, K=128, N=128), tile 64x128.
// Epilogue: es/ed dot products + exp tables + smem-staged TRANSPOSED bf16
// hi/lo Wh store (coalesced STG.128 instead of scattered STG.16).
// ---------------------------------------------------------------------------
#define TBP 130                          // transpose buffer pitch (bf16), odd u32
__global__ __launch_bounds__(256) void k_gemm(const float* __restrict__ h,
                                              const float* __restrict__ W,
                                              const float* __restrict__ a) {
    __shared__ union {
        struct { float hs[64][33]; float Ws[32][128]; } mm;   // 24832 B
        __nv_bfloat16 tb[2][64 * TBP];                        // 33280 B
    } sm;
    __shared__ float sred[64][17];
    __shared__ float dred[64][17];

    const int row0 = blockIdx.x * 64;
    const int tid  = threadIdx.x;
    const int tx   = tid & 15;
    const int ty   = tid >> 4;

    u64 acc2[4][4];
#pragma unroll
    for (int r = 0; r < 4; r++)
#pragma unroll
        for (int d = 0; d < 4; d++) acc2[r][d] = 0ull;

    for (int k0 = 0; k0 < 128; k0 += 32) {
        __syncthreads();
#pragma unroll
        for (int l = 0; l < 2; l++) {
            int idx = tid + l * 256;
            int r = idx >> 3, c4 = (idx & 7) * 4;
            float4 v = *(const float4*)&h[(size_t)(row0 + r) * 128 + k0 + c4];
            sm.mm.hs[r][c4 + 0] = v.x; sm.mm.hs[r][c4 + 1] = v.y;
            sm.mm.hs[r][c4 + 2] = v.z; sm.mm.hs[r][c4 + 3] = v.w;
        }
#pragma unroll
        for (int l = 0; l < 4; l++) {
            int idx = tid + l * 256;
            int kk = idx >> 5, dc = (idx & 31) * 4;
            *(float4*)&sm.mm.Ws[kk][dc] = *(const float4*)&W[(k0 + kk) * 128 + dc];
        }
        __syncthreads();
#pragma unroll 8
        for (int k = 0; k < 32; k++) {
            ulonglong2 wa = *(const ulonglong2*)&sm.mm.Ws[k][tx * 8];
            ulonglong2 wb = *(const ulonglong2*)&sm.mm.Ws[k][tx * 8 + 4];
#pragma unroll
            for (int r = 0; r < 4; r++) {
                float hv = sm.mm.hs[ty + r * 16][k];
                u64 h2 = pack2(hv, hv);
                ffma2(acc2[r][0], h2, wa.x);
                ffma2(acc2[r][1], h2, wa.y);
                ffma2(acc2[r][2], h2, wb.x);
                ffma2(acc2[r][3], h2, wb.y);
            }
        }
    }
    __syncthreads();   // mainloop reads of hs/Ws done before tb overwrite

    float a_s[8], a_d[8];
#pragma unroll
    for (int d = 0; d < 8; d++) {
        a_s[d] = a[tx * 8 + d];
        a_d[d] = a[128 + tx * 8 + d];
    }

#pragma unroll
    for (int r = 0; r < 4; r++) {
        int rl = ty + r * 16;              // local j (0..63)
        float v[8];
        float2 p;
        p = unpack2(acc2[r][0]); v[0] = p.x; v[1] = p.y;
        p = unpack2(acc2[r][1]); v[2] = p.x; v[3] = p.y;
        p = unpack2(acc2[r][2]); v[4] = p.x; v[5] = p.y;
        p = unpack2(acc2[r][3]); v[6] = p.x; v[7] = p.y;
        float s = 0.f, dd = 0.f;
#pragma unroll
        for (int d = 0; d < 8; d += 2) {
            s  += v[d] * a_s[d]     + v[d + 1] * a_s[d + 1];
            dd += v[d] * a_d[d]     + v[d + 1] * a_d[d + 1];
            __nv_bfloat162 hp = __floats2bfloat162_rn(v[d], v[d + 1]);
            float l0 = v[d]     - __bfloat162float(hp.x);
            float l1 = v[d + 1] - __bfloat162float(hp.y);
            __nv_bfloat162 lp = __floats2bfloat162_rn(l0, l1);
            *(u32*)&sm.tb[0][rl * TBP + tx * 8 + d] = *(u32*)&hp;
            *(u32*)&sm.tb[1][rl * TBP + tx * 8 + d] = *(u32*)&lp;
        }
        sred[rl][tx] = s;
        dred[rl][tx] = dd;
    }
    __syncthreads();

    // es/ed reduction + exp tables
    if (tid < 64) {
        float s = 0.f, dd = 0.f;
#pragma unroll
        for (int t = 0; t < 16; t++) { s += sred[tid][t]; dd += dred[tid][t]; }
        int n = row0 + tid;
        g_es[n] = s;  g_ed[n] = dd;
        g_F[n] = expf(s);         g_f[n] = expf(0.2f * s);
        g_G[n] = expf(dd);        g_g[n] = expf(0.2f * dd);
    }

    // transposed coalesced store: thread = d-row (tid>>1), j-half (tid&1)
    {
        const int bts   = row0 >> 9;
        const int jcol0 = row0 & 511;
        const int dr    = tid >> 1;
        const int jb    = (tid & 1) * 32;
        size_t gbase = ((size_t)bts * 128 + dr) * 512 + jcol0 + jb;
#pragma unroll
        for (int buf = 0; buf < 2; buf++) {
            __nv_bfloat16* gdst = buf ? g_WhT_lo : g_WhT_hi;
            const __nv_bfloat16* src = sm.tb[buf];
#pragma unroll
            for (int q = 0; q < 4; q++) {
                u16 w[8];
#pragma unroll
                for (int e = 0; e < 8; e++)
                    w[e] = *(const u16*)&src[(jb + q * 8 + e) * TBP + dr];
                *(uint4*)&gdst[gbase + q * 8] = *(uint4*)w;
            }
        }
    }
}

// ---------------------------------------------------------------------------
// Kernel 2: adjacency -> bitmask
// ---------------------------------------------------------------------------
__global__ __launch_bounds__(256) void k_adjbits(const int* __restrict__ adj) {
    int idx = blockIdx.x * 256 + threadIdx.x;
    int i = idx >> 4, w = idx & 15;
    unsigned bits = 0;
#pragma unroll
    for (int b = 0; b < 32; b++)
        if (adj[i * NN + w * 32 + b] > 0) bits |= (1u << b);
    g_adjbits[idx] = bits;
}

// ---------------------------------------------------------------------------
// Kernel 3: tensor-core (mma.sync bf16) fused masked-softmax-attention.
// D[d][i] = sum_j WhT[d][j] * C[i][j];  out[i][d] = D[d][i] / den[i]
// (unchanged from R10 passing version)
// ---------------------------------------------------------------------------
#define PITCH_B 144                      // 72 bf16 per row
__global__ __launch_bounds__(256) void k_attn(float* __restrict__ out) {
    extern __shared__ char dyn[];
    char* smA_hi = dyn;                  // [128][72] bf16 = 18432 B
    char* smA_lo = dyn + 18432;
    char* smB_hi = dyn + 36864;
    char* smB_lo = dyn + 55296;          // total 73728 B

    __shared__ unsigned bitsS[128 * 16];
    __shared__ float edS[64], GS[64], gS[64];
    __shared__ float denS[256];
    __shared__ float invD[128];

    const int tid  = threadIdx.x;
    const int lane = tid & 31;
    const int wp   = tid >> 5;
    const int bt   = blockIdx.x >> 2;
    const int tile = blockIdx.x & 3;
    const int base = bt * NN;
    const int i0   = tile * 128;

#pragma unroll
    for (int l = 0; l < 2; l++) {
        int idx4 = tid + l * 256;
        int r = idx4 >> 2, w4 = (idx4 & 3) * 4;
        *(uint4*)&bitsS[r * 16 + w4] = *(const uint4*)&g_adjbits[(i0 + r) * 16 + w4];
    }

    const int i    = tid >> 1;
    const int half = tid & 1;
    const float esv = g_es[base + i0 + i];
    const float Fv  = g_F[base + i0 + i];
    const float fv  = g_f[base + i0 + i];
    float den = 0.f;

    const __nv_bfloat16* srcHi = g_WhT_hi + (size_t)bt * 128 * 512;
    const __nv_bfloat16* srcLo = g_WhT_lo + (size_t)bt * 128 * 512;

    const int arow  = (lane & 7) + ((lane >> 3) & 1) * 8;
    const int akoff = (lane >> 4) * 8;
    const int brow  = (lane & 7) + (lane >> 4) * 8;
    const int bkoff = ((lane >> 3) & 1) * 8;
    const u32 adAhi = smem_u32(smA_hi) + (wp * 16 + arow) * PITCH_B + akoff * 2;
    const u32 adAlo = smem_u32(smA_lo) + (wp * 16 + arow) * PITCH_B + akoff * 2;
    const u32 adBhi = smem_u32(smB_hi) + brow * PITCH_B + bkoff * 2;
    const u32 adBlo = smem_u32(smB_lo) + brow * PITCH_B + bkoff * 2;

    float acc[16][4];
#pragma unroll
    for (int nf = 0; nf < 16; nf++)
#pragma unroll
        for (int q = 0; q < 4; q++) acc[nf][q] = 0.f;

    for (int ch = 0; ch < 8; ch++) {
        const int j0 = ch * 64;
        __syncthreads();
        if (tid < 64)       edS[tid]      = g_ed[base + j0 + tid];
        else if (tid < 128) GS[tid - 64]  = g_G[base + j0 + tid - 64];
        else if (tid < 192) gS[tid - 128] = g_g[base + j0 + tid - 128];
        {
            const int slot = tid & 7;
            const int drow = tid >> 3;
#pragma unroll
            for (int it = 0; it < 4; it++) {
                int d = drow + it * 32;
                size_t off = (size_t)d * 512 + j0 + slot * 8;
                *(uint4*)(smA_hi + d * PITCH_B + slot * 16) = *(const uint4*)(srcHi + off);
                *(uint4*)(smA_lo + d * PITCH_B + slot * 16) = *(const uint4*)(srcLo + off);
            }
        }
        __syncthreads();
        {
            unsigned bits = bitsS[i * 16 + ch * 2 + half];
#pragma unroll
            for (int jj = 0; jj < 32; jj += 2) {
                int j = half * 32 + jj;
                float c0 = 0.f, c1 = 0.f;
                if ((bits >> jj) & 1u) {
                    float t = esv + edS[j];
                    c0 = (t > 0.f) ? Fv * GS[j] : fv * gS[j];
                }
                if ((bits >> (jj + 1)) & 1u) {
                    float t = esv + edS[j + 1];
                    c1 = (t > 0.f) ? Fv * GS[j + 1] : fv * gS[j + 1];
                }
                den += c0 + c1;
                __nv_bfloat162 hp = __floats2bfloat162_rn(c0, c1);
                float l0 = c0 - __bfloat162float(hp.x);
                float l1 = c1 - __bfloat162float(hp.y);
                __nv_bfloat162 lp = __floats2bfloat162_rn(l0, l1);
                *(u32*)(smB_hi + i * PITCH_B + j * 2) = *(u32*)&hp;
                *(u32*)(smB_lo + i * PITCH_B + j * 2) = *(u32*)&lp;
            }
        }
        __syncthreads();
#pragma unroll
        for (int ks = 0; ks < 4; ks++) {
            u32 ahi[4], alo[4];
            LDSM4(ahi, adAhi + ks * 32);
            LDSM4(alo, adAlo + ks * 32);
#pragma unroll
            for (int p = 0; p < 8; p++) {
                u32 bhi[4], blo[4];
                LDSM4(bhi, adBhi + p * (16 * PITCH_B) + ks * 32);
                LDSM4(blo, adBlo + p * (16 * PITCH_B) + ks * 32);
                mma_bf16(acc[2 * p],     ahi, bhi);
                mma_bf16(acc[2 * p],     ahi, blo);
                mma_bf16(acc[2 * p],     alo, bhi);
                mma_bf16(acc[2 * p + 1], ahi, bhi + 2);
                mma_bf16(acc[2 * p + 1], ahi, blo + 2);
                mma_bf16(acc[2 * p + 1], alo, bhi + 2);
            }
        }
    }

    denS[tid] = den;
    __syncthreads();
    if (tid < 128) invD[tid] = 1.0f / (denS[2 * tid] + denS[2 * tid + 1]);
    __syncthreads();

    {
        const int dl = wp * 16 + (lane >> 2);
        const int il = 2 * (lane & 3);
#pragma unroll
        for (int nf = 0; nf < 16; nf++) {
            int ir = nf * 8 + il;
            float v0 = invD[ir], v1 = invD[ir + 1];
            float* p0 = out + (size_t)(base + i0 + ir) * 128 + dl;
            p0[0]        = acc[nf][0] * v0;
            p0[128]      = acc[nf][1] * v1;
            p0[8]        = acc[nf][2] * v0;
            p0[128 + 8]  = acc[nf][3] * v1;
        }
    }
}

// ---------------------------------------------------------------------------
extern "C" void kernel_launch(void* const* d_in, const int* in_sizes, int n_in,
                              void* d_out, int out_size) {
    const float* h   = (const float*)d_in[0];   // (4,32,512,128) f32
    const int*   adj = (const int*)d_in[1];     // (512,512) i32
    const float* W   = (const float*)d_in[2];   // (128,128) f32
    const float* a   = (const float*)d_in[3];   // (256,) f32
    float* out = (float*)d_out;                 // (4,32,512,128) f32

    const int attn_smem = 4 * 128 * PITCH_B;    // 73728 B
    cudaFuncSetAttribute(k_attn, cudaFuncAttributeMaxDynamicSharedMemorySize,
                         attn_smem);

    k_gemm<<<NROWS / 64, 256>>>(h, W, a);       // Wh^T(bf16 hi/lo) + exp tables
    k_adjbits<<<(NN * 16) / 256, 256>>>(adj);   // adj bitmask
    k_attn<<<BT * 4, 256, attn_smem>>>(out);    // mma.sync softmax-attention
}

// round 13
// speedup vs baseline: 1.6939x; 1.0021x over previous
#include <cuda_runtime.h>
#include <cuda_bf16.h>
#include <cstdint>

// Problem constants: B=4, T=32 -> BT=128 slices; N=512 nodes; F_in=D=128.
#define BT    128
#define NN    512
#define DD    128
#define NROWS (BT * NN)       // 65536 total node-rows

typedef unsigned long long u64;
typedef unsigned int       u32;
typedef unsigned short     u16;

// Scratch (allocation-free: __device__ globals)
__device__ float g_es[NROWS], g_ed[NROWS];
__device__ float g_F[NROWS], g_f[NROWS];           // exp(es), exp(0.2*es)
__device__ float g_G[NROWS], g_g[NROWS];           // exp(ed), exp(0.2*ed)
__device__ unsigned g_adjbits[NN * 16];            // bit j%32 of word [i][j/32]
// Wh transposed per slice, split into bf16 hi/lo: index [(bt*128 + d)*512 + j]
__device__ __align__(16) __nv_bfloat16 g_WhT_hi[NROWS * DD];
__device__ __align__(16) __nv_bfloat16 g_WhT_lo[NROWS * DD];

// ---- f32x2 helpers (k_gemm mainloop only) ----
__device__ __forceinline__ u64 pack2(float lo, float hi) {
    u64 r; asm("mov.b64 %0, {%1, %2};" : "=l"(r) : "f"(lo), "f"(hi)); return r;
}
__device__ __forceinline__ void ffma2(u64& d, u64 a, u64 b) {
    asm("fma.rn.f32x2 %0, %1, %2, %0;" : "+l"(d) : "l"(a), "l"(b));
}
__device__ __forceinline__ float2 unpack2(u64 v) {
    float2 f; asm("mov.b64 {%0, %1}, %2;" : "=f"(f.x), "=f"(f.y) : "l"(v)); return f;
}

__device__ __forceinline__ u32 smem_u32(const void* p) {
    u32 a;
    asm("{ .reg .u64 t; cvta.to.shared.u64 t, %1; cvt.u32.u64 %0, t; }"
        : "=r"(a) : "l"(p));
    return a;
}

// ---- family-portable tensor ops: ldmatrix + mma.sync (bf16, f32 acc) ----
#define LDSM4(r, addr) \
    asm volatile("ldmatrix.sync.aligned.m8n8.x4.shared.b16 {%0,%1,%2,%3}, [%4];" \
        : "=r"((r)[0]), "=r"((r)[1]), "=r"((r)[2]), "=r"((r)[3]) : "r"(addr))

__device__ __forceinline__ void mma_bf16(float* d, const u32* a, const u32* b) {
    asm volatile("mma.sync.aligned.m16n8k16.row.col.f32.bf16.bf16.f32 "
        "{%0,%1,%2,%3}, {%4,%5,%6,%7}, {%8,%9}, {%0,%1,%2,%3};"
        : "+f"(d[0]), "+f"(d[1]), "+f"(d[2]), "+f"(d[3])
        : "r"(a[0]), "r"(a[1]), "r"(a[2]), "r"(a[3]), "r"(b[0]), "r"(b[1]));
}

// ---------------------------------------------------------------------------
// Kernel 1: Wh = h @ W  (M=65536, K=128, N=128), tile 64x128.
// Epilogue: es/ed dot products + exp tables + smem-staged TRANSPOSED bf16
// hi/lo Wh store (coalesced STG.128 instead of scattered STG.16).
// ---------------------------------------------------------------------------
#define TBP 130                          // transpose buffer pitch (bf16), odd u32
__global__ __launch_bounds__(256) void k_gemm(const float* __restrict__ h,
                                              const float* __restrict__ W,
                                              const float* __restrict__ a) {
    __shared__ union {
        struct { float hs[64][33]; float Ws[32][128]; } mm;   // 24832 B
        __nv_bfloat16 tb[2][64 * TBP];                        // 33280 B
    } sm;
    __shared__ float sred[64][17];
    __shared__ float dred[64][17];

    const int row0 = blockIdx.x * 64;
    const int tid  = threadIdx.x;
    const int tx   = tid & 15;
    const int ty   = tid >> 4;

    u64 acc2[4][4];
#pragma unroll
    for (int r = 0; r < 4; r++)
#pragma unroll
        for (int d = 0; d < 4; d++) acc2[r][d] = 0ull;

    for (int k0 = 0; k0 < 128; k0 += 32) {
        __syncthreads();
#pragma unroll
        for (int l = 0; l < 2; l++) {
            int idx = tid + l * 256;
            int r = idx >> 3, c4 = (idx & 7) * 4;
            float4 v = *(const float4*)&h[(size_t)(row0 + r) * 128 + k0 + c4];
            sm.mm.hs[r][c4 + 0] = v.x; sm.mm.hs[r][c4 + 1] = v.y;
            sm.mm.hs[r][c4 + 2] = v.z; sm.mm.hs[r][c4 + 3] = v.w;
        }
#pragma unroll
        for (int l = 0; l < 4; l++) {
            int idx = tid + l * 256;
            int kk = idx >> 5, dc = (idx & 31) * 4;
            *(float4*)&sm.mm.Ws[kk][dc] = *(const float4*)&W[(k0 + kk) * 128 + dc];
        }
        __syncthreads();
#pragma unroll 8
        for (int k = 0; k < 32; k++) {
            ulonglong2 wa = *(const ulonglong2*)&sm.mm.Ws[k][tx * 8];
            ulonglong2 wb = *(const ulonglong2*)&sm.mm.Ws[k][tx * 8 + 4];
#pragma unroll
            for (int r = 0; r < 4; r++) {
                float hv = sm.mm.hs[ty + r * 16][k];
                u64 h2 = pack2(hv, hv);
                ffma2(acc2[r][0], h2, wa.x);
                ffma2(acc2[r][1], h2, wa.y);
                ffma2(acc2[r][2], h2, wb.x);
                ffma2(acc2[r][3], h2, wb.y);
            }
        }
    }
    __syncthreads();   // mainloop reads of hs/Ws done before tb overwrite

    float a_s[8], a_d[8];
#pragma unroll
    for (int d = 0; d < 8; d++) {
        a_s[d] = a[tx * 8 + d];
        a_d[d] = a[128 + tx * 8 + d];
    }

#pragma unroll
    for (int r = 0; r < 4; r++) {
        int rl = ty + r * 16;              // local j (0..63)
        float v[8];
        float2 p;
        p = unpack2(acc2[r][0]); v[0] = p.x; v[1] = p.y;
        p = unpack2(acc2[r][1]); v[2] = p.x; v[3] = p.y;
        p = unpack2(acc2[r][2]); v[4] = p.x; v[5] = p.y;
        p = unpack2(acc2[r][3]); v[6] = p.x; v[7] = p.y;
        float s = 0.f, dd = 0.f;
#pragma unroll
        for (int d = 0; d < 8; d += 2) {
            s  += v[d] * a_s[d]     + v[d + 1] * a_s[d + 1];
            dd += v[d] * a_d[d]     + v[d + 1] * a_d[d + 1];
            __nv_bfloat162 hp = __floats2bfloat162_rn(v[d], v[d + 1]);
            float l0 = v[d]     - __bfloat162float(hp.x);
            float l1 = v[d + 1] - __bfloat162float(hp.y);
            __nv_bfloat162 lp = __floats2bfloat162_rn(l0, l1);
            *(u32*)&sm.tb[0][rl * TBP + tx * 8 + d] = *(u32*)&hp;
            *(u32*)&sm.tb[1][rl * TBP + tx * 8 + d] = *(u32*)&lp;
        }
        sred[rl][tx] = s;
        dred[rl][tx] = dd;
    }
    __syncthreads();

    // es/ed reduction + exp tables
    if (tid < 64) {
        float s = 0.f, dd = 0.f;
#pragma unroll
        for (int t = 0; t < 16; t++) { s += sred[tid][t]; dd += dred[tid][t]; }
        int n = row0 + tid;
        g_es[n] = s;  g_ed[n] = dd;
        g_F[n] = expf(s);         g_f[n] = expf(0.2f * s);
        g_G[n] = expf(dd);        g_g[n] = expf(0.2f * dd);
    }

    // transposed coalesced store: thread = d-row (tid>>1), j-half (tid&1)
    {
        const int bts   = row0 >> 9;
        const int jcol0 = row0 & 511;
        const int dr    = tid >> 1;
        const int jb    = (tid & 1) * 32;
        size_t gbase = ((size_t)bts * 128 + dr) * 512 + jcol0 + jb;
#pragma unroll
        for (int buf = 0; buf < 2; buf++) {
            __nv_bfloat16* gdst = buf ? g_WhT_lo : g_WhT_hi;
            const __nv_bfloat16* src = sm.tb[buf];
#pragma unroll
            for (int q = 0; q < 4; q++) {
                u16 w[8];
#pragma unroll
                for (int e = 0; e < 8; e++)
                    w[e] = *(const u16*)&src[(jb + q * 8 + e) * TBP + dr];
                *(uint4*)&gdst[gbase + q * 8] = *(uint4*)w;
            }
        }
    }
}

// ---------------------------------------------------------------------------
// Kernel 2: adjacency -> bitmask
// ---------------------------------------------------------------------------
__global__ __launch_bounds__(256) void k_adjbits(const int* __restrict__ adj) {
    int idx = blockIdx.x * 256 + threadIdx.x;
    int i = idx >> 4, w = idx & 15;
    unsigned bits = 0;
#pragma unroll
    for (int b = 0; b < 32; b++)
        if (adj[i * NN + w * 32 + b] > 0) bits |= (1u << b);
    g_adjbits[idx] = bits;
}

// ---------------------------------------------------------------------------
// Kernel 3: tensor-core (mma.sync bf16) fused masked-softmax-attention.
// D[d][i] = sum_j WhT[d][j] * C[i][j];  out[i][d] = D[d][i] / den[i]
// (unchanged from R10 passing version)
// ---------------------------------------------------------------------------
#define PITCH_B 144                      // 72 bf16 per row
__global__ __launch_bounds__(256) void k_attn(float* __restrict__ out) {
    extern __shared__ char dyn[];
    char* smA_hi = dyn;                  // [128][72] bf16 = 18432 B
    char* smA_lo = dyn + 18432;
    char* smB_hi = dyn + 36864;
    char* smB_lo = dyn + 55296;          // total 73728 B

    __shared__ unsigned bitsS[128 * 16];
    __shared__ float edS[64], GS[64], gS[64];
    __shared__ float denS[256];
    __shared__ float invD[128];

    const int tid  = threadIdx.x;
    const int lane = tid & 31;
    const int wp   = tid >> 5;
    const int bt   = blockIdx.x >> 2;
    const int tile = blockIdx.x & 3;
    const int base = bt * NN;
    const int i0   = tile * 128;

#pragma unroll
    for (int l = 0; l < 2; l++) {
        int idx4 = tid + l * 256;
        int r = idx4 >> 2, w4 = (idx4 & 3) * 4;
        *(uint4*)&bitsS[r * 16 + w4] = *(const uint4*)&g_adjbits[(i0 + r) * 16 + w4];
    }

    const int i    = tid >> 1;
    const int half = tid & 1;
    const float esv = g_es[base + i0 + i];
    const float Fv  = g_F[base + i0 + i];
    const float fv  = g_f[base + i0 + i];
    float den = 0.f;

    const __nv_bfloat16* srcHi = g_WhT_hi + (size_t)bt * 128 * 512;
    const __nv_bfloat16* srcLo = g_WhT_lo + (size_t)bt * 128 * 512;

    const int arow  = (lane & 7) + ((lane >> 3) & 1) * 8;
    const int akoff = (lane >> 4) * 8;
    const int brow  = (lane & 7) + (lane >> 4) * 8;
    const int bkoff = ((lane >> 3) & 1) * 8;
    const u32 adAhi = smem_u32(smA_hi) + (wp * 16 + arow) * PITCH_B + akoff * 2;
    const u32 adAlo = smem_u32(smA_lo) + (wp * 16 + arow) * PITCH_B + akoff * 2;
    const u32 adBhi = smem_u32(smB_hi) + brow * PITCH_B + bkoff * 2;
    const u32 adBlo = smem_u32(smB_lo) + brow * PITCH_B + bkoff * 2;

    float acc[16][4];
#pragma unroll
    for (int nf = 0; nf < 16; nf++)
#pragma unroll
        for (int q = 0; q < 4; q++) acc[nf][q] = 0.f;

    for (int ch = 0; ch < 8; ch++) {
        const int j0 = ch * 64;
        __syncthreads();
        if (tid < 64)       edS[tid]      = g_ed[base + j0 + tid];
        else if (tid < 128) GS[tid - 64]  = g_G[base + j0 + tid - 64];
        else if (tid < 192) gS[tid - 128] = g_g[base + j0 + tid - 128];
        {
            const int slot = tid & 7;
            const int drow = tid >> 3;
#pragma unroll
            for (int it = 0; it < 4; it++) {
                int d = drow + it * 32;
                size_t off = (size_t)d * 512 + j0 + slot * 8;
                *(uint4*)(smA_hi + d * PITCH_B + slot * 16) = *(const uint4*)(srcHi + off);
                *(uint4*)(smA_lo + d * PITCH_B + slot * 16) = *(const uint4*)(srcLo + off);
            }
        }
        __syncthreads();
        {
            unsigned bits = bitsS[i * 16 + ch * 2 + half];
#pragma unroll
            for (int jj = 0; jj < 32; jj += 2) {
                int j = half * 32 + jj;
                float c0 = 0.f, c1 = 0.f;
                if ((bits >> jj) & 1u) {
                    float t = esv + edS[j];
                    c0 = (t > 0.f) ? Fv * GS[j] : fv * gS[j];
                }
                if ((bits >> (jj + 1)) & 1u) {
                    float t = esv + edS[j + 1];
                    c1 = (t > 0.f) ? Fv * GS[j + 1] : fv * gS[j + 1];
                }
                den += c0 + c1;
                __nv_bfloat162 hp = __floats2bfloat162_rn(c0, c1);
                float l0 = c0 - __bfloat162float(hp.x);
                float l1 = c1 - __bfloat162float(hp.y);
                __nv_bfloat162 lp = __floats2bfloat162_rn(l0, l1);
                *(u32*)(smB_hi + i * PITCH_B + j * 2) = *(u32*)&hp;
                *(u32*)(smB_lo + i * PITCH_B + j * 2) = *(u32*)&lp;
            }
        }
        __syncthreads();
#pragma unroll
        for (int ks = 0; ks < 4; ks++) {
            u32 ahi[4], alo[4];
            LDSM4(ahi, adAhi + ks * 32);
            LDSM4(alo, adAlo + ks * 32);
#pragma unroll
            for (int p = 0; p < 8; p++) {
                u32 bhi[4], blo[4];
                LDSM4(bhi, adBhi + p * (16 * PITCH_B) + ks * 32);
                LDSM4(blo, adBlo + p * (16 * PITCH_B) + ks * 32);
                mma_bf16(acc[2 * p],     ahi, bhi);
                mma_bf16(acc[2 * p],     ahi, blo);
                mma_bf16(acc[2 * p],     alo, bhi);
                mma_bf16(acc[2 * p + 1], ahi, bhi + 2);
                mma_bf16(acc[2 * p + 1], ahi, blo + 2);
                mma_bf16(acc[2 * p + 1], alo, bhi + 2);
            }
        }
    }

    denS[tid] = den;
    __syncthreads();
    if (tid < 128) invD[tid] = 1.0f / (denS[2 * tid] + denS[2 * tid + 1]);
    __syncthreads();

    {
        const int dl = wp * 16 + (lane >> 2);
        const int il = 2 * (lane & 3);
#pragma unroll
        for (int nf = 0; nf < 16; nf++) {
            int ir = nf * 8 + il;
            float v0 = invD[ir], v1 = invD[ir + 1];
            float* p0 = out + (size_t)(base + i0 + ir) * 128 + dl;
            p0[0]        = acc[nf][0] * v0;
            p0[128]      = acc[nf][1] * v1;
            p0[8]        = acc[nf][2] * v0;
            p0[128 + 8]  = acc[nf][3] * v1;
        }
    }
}

// ---------------------------------------------------------------------------
extern "C" void kernel_launch(void* const* d_in, const int* in_sizes, int n_in,
                              void* d_out, int out_size) {
    const float* h   = (const float*)d_in[0];   // (4,32,512,128) f32
    const int*   adj = (const int*)d_in[1];     // (512,512) i32
    const float* W   = (const float*)d_in[2];   // (128,128) f32
    const float* a   = (const float*)d_in[3];   // (256,) f32
    float* out = (float*)d_out;                 // (4,32,512,128) f32

    const int attn_smem = 4 * 128 * PITCH_B;    // 73728 B
    cudaFuncSetAttribute(k_attn, cudaFuncAttributeMaxDynamicSharedMemorySize,
                         attn_smem);

    k_gemm<<<NROWS / 64, 256>>>(h, W, a);       // Wh^T(bf16 hi/lo) + exp tables
    k_adjbits<<<(NN * 16) / 256, 256>>>(adj);   // adj bitmask
    k_attn<<<BT * 4, 256, attn_smem>>>(out);    // mma.sync softmax-attention
}